// round 1
// baseline (speedup 1.0000x reference)
#include <cuda_runtime.h>
#include <cuda_bf16.h>
#include <math.h>

// Shapes (fixed for this problem)
#define NN   4096
#define NV   3
#define MM   16
#define EE   256
#define HH   8
#define DD   32
#define NR   (NN*NV)          // 12288 rows of g_src
#define SQRT_E 16.0f
#define SCALING 0.17677669529663687f   // 32^-0.5

// ---------------- scratch (device globals; no allocation allowed) -------------
__device__ float d_g_src[NR*EE];       // [N,n,E] scaled
__device__ float d_h2[NN*2*EE];        // [N, 512] = [g2 | h_src]
__device__ float d_gram[NN*1024];      // [N, 32*32]
__device__ float d_t1[NN*512];         // relu(gram@W_g1+b)
__device__ float d_qb[NN*EE];
__device__ float d_kb[NN*EE];
__device__ float d_vb[NN*EE];
__device__ float d_vgb[NR*EE];
__device__ float d_outv[NN*EE];
__device__ float d_outg[NR*EE];
__device__ float d_hnew[NN*EE];
__device__ float d_gnew[NR*EE];

// ---------------- g_src = (equ @ W_equ) * 16 ----------------------------------
__global__ void gsrc_kernel(const float* __restrict__ equ,
                            const float* __restrict__ W_equ)
{
    __shared__ float es[MM];
    int r = blockIdx.x;                 // 0..12287
    int e = threadIdx.x;                // 0..255
    if (e < MM) es[e] = equ[r*MM + e];
    __syncthreads();
    float acc = 0.f;
#pragma unroll
    for (int m = 0; m < MM; m++) acc += es[m] * W_equ[m*EE + e];
    d_g_src[r*EE + e] = acc * SQRT_E;
}

// ---------------- h_src = h*16  (into h2[:,256:512]) --------------------------
__global__ void hsrc_kernel(const float* __restrict__ h)
{
    int i = blockIdx.x, e = threadIdx.x;
    d_h2[i*512 + 256 + e] = h[i*EE + e] * SQRT_E;
}

// ---------------- g2p + Gram ---------------------------------------------------
__global__ void gram_kernel(const float* __restrict__ W_gproj)
{
    __shared__ float gs[NV][EE];
    __shared__ float g2p[NV][32];
    int node = blockIdx.x;
    int t = threadIdx.x;
#pragma unroll
    for (int i = 0; i < NV; i++) gs[i][t] = d_g_src[(node*NV + i)*EE + t];
    __syncthreads();
    if (t < 96) {
        int i = t >> 5, a = t & 31;
        float acc = 0.f;
#pragma unroll 4
        for (int k2 = 0; k2 < EE; k2++) acc += gs[i][k2] * W_gproj[k2*32 + a];
        g2p[i][a] = acc;
    }
    __syncthreads();
#pragma unroll
    for (int o = t; o < 1024; o += 256) {
        int a = o >> 5, b = o & 31;
        float acc = g2p[0][a]*g2p[0][b] + g2p[1][a]*g2p[1][b] + g2p[2][a]*g2p[2][b];
        d_gram[node*1024 + o] = acc;
    }
}

// ---------------- generic tiled fp32 GEMM -------------------------------------
// C[row*ldc+col] = post( alpha*(A@B + bias) + resid[row*ldr+col] )
template<bool RELU, bool BIAS, bool RES>
__global__ __launch_bounds__(256)
void gemm_kernel(const float* __restrict__ A, const float* __restrict__ B,
                 const float* __restrict__ bias, const float* __restrict__ resid,
                 float* __restrict__ C, int K, int Nn,
                 int ldr, int ldc, float alpha)
{
    __shared__ float As[16][64];
    __shared__ float Bs[16][64];
    int tid = threadIdx.x;
    int tx = tid & 15, ty = tid >> 4;
    int m0 = blockIdx.y * 64, n0 = blockIdx.x * 64;
    int arow = tid >> 2;            // 0..63
    int acol = (tid & 3) * 4;       // 0..12
    int brow = tid >> 4;            // 0..15
    int bcol = (tid & 15) * 4;
    float acc[4][4] = {};

    for (int k0 = 0; k0 < K; k0 += 16) {
        float4 a4 = *(const float4*)&A[(m0 + arow)*K + k0 + acol];
        float4 b4 = *(const float4*)&B[(k0 + brow)*Nn + n0 + bcol];
        __syncthreads();
        As[acol+0][arow] = a4.x; As[acol+1][arow] = a4.y;
        As[acol+2][arow] = a4.z; As[acol+3][arow] = a4.w;
        *(float4*)&Bs[brow][bcol] = b4;
        __syncthreads();
#pragma unroll
        for (int kk = 0; kk < 16; kk++) {
            float4 av = *(const float4*)&As[kk][ty*4];
            float4 bv = *(const float4*)&Bs[kk][tx*4];
            float ar[4] = {av.x, av.y, av.z, av.w};
            float br[4] = {bv.x, bv.y, bv.z, bv.w};
#pragma unroll
            for (int i = 0; i < 4; i++)
#pragma unroll
                for (int j = 0; j < 4; j++)
                    acc[i][j] += ar[i]*br[j];
        }
    }
    // epilogue
#pragma unroll
    for (int i = 0; i < 4; i++) {
        int row = m0 + ty*4 + i;
        float4 o;
        float vals[4];
#pragma unroll
        for (int j = 0; j < 4; j++) {
            int col = n0 + tx*4 + j;
            float v = acc[i][j];
            if (BIAS) v += bias[col];
            v *= alpha;
            if (RES)  v += resid[row*ldr + col];
            if (RELU) v = fmaxf(v, 0.f);
            vals[j] = v;
        }
        o.x = vals[0]; o.y = vals[1]; o.z = vals[2]; o.w = vals[3];
        *(float4*)&C[row*ldc + n0 + tx*4] = o;
    }
}

// ---------------- fused flash attention ---------------------------------------
// grid (128, 8): 32 query rows x one head per block; streams K/V in 64-row tiles.
// Combined value width 128 = [v | vg0 | vg1 | vg2] per head.
#define TQ 32
#define TK 64
#define ATTN_SMEM_FLOATS (TQ*36 + TK*36 + TK*128 + TQ*65 + 3*TQ)
#define ATTN_SMEM_BYTES  (ATTN_SMEM_FLOATS*4)

__global__ __launch_bounds__(256, 4)
void attn_kernel(const float* __restrict__ q, const float* __restrict__ k,
                 const float* __restrict__ v, const float* __restrict__ vg)
{
    extern __shared__ float sm[];
    float* Qs   = sm;                  // [32][36]
    float* Ks   = Qs + TQ*36;          // [64][36]
    float* Vs   = Ks + TK*36;          // [64][128]
    float* Ss   = Vs + TK*128;         // [32][65]
    float* rmax = Ss + TQ*65;          // [32]
    float* rsum = rmax + TQ;
    float* ralf = rsum + TQ;

    int tid  = threadIdx.x;
    int lane = tid & 31;
    int w    = tid >> 5;               // 0..7
    int hh   = blockIdx.y;
    int qbase = blockIdx.x * TQ;
    int hoff = hh * DD;

    // load Q tile [32][32]
    {
        int row = tid >> 3, c4 = (tid & 7) * 4;
        *(float4*)&Qs[row*36 + c4] = *(const float4*)&q[(qbase+row)*EE + hoff + c4];
    }
    if (tid < TQ) { rmax[tid] = -1e30f; rsum[tid] = 0.f; }
    float acc[4][4] = {};

    for (int kb = 0; kb < NN; kb += TK) {
        __syncthreads();
        // K tile [64][32]
#pragma unroll
        for (int l = 0; l < 2; l++) {
            int idx = tid + l*256;
            int row = idx >> 3, c4 = (idx & 7)*4;
            *(float4*)&Ks[row*36 + c4] = *(const float4*)&k[(kb+row)*EE + hoff + c4];
        }
        // V combined tile [64][128]
#pragma unroll
        for (int l = 0; l < 8; l++) {
            int idx = tid + l*256;
            int row = idx >> 5;
            int c4  = (idx & 31) * 4;
            const float* src;
            if (c4 < 32) {
                src = &v[(kb+row)*EE + hoff + c4];
            } else {
                int iv = (c4 - 32) >> 5, dcol = (c4 - 32) & 31;
                src = &vg[((kb+row)*NV + iv)*EE + hoff + dcol];
            }
            *(float4*)&Vs[row*128 + c4] = *(const float4*)src;
        }
        __syncthreads();
        // S = Q K^T  (rows 4w+i, cols 2*lane+j)
        {
            float s[4][2] = {};
#pragma unroll
            for (int k4 = 0; k4 < DD; k4 += 4) {
                float4 a[4], b[2];
#pragma unroll
                for (int i = 0; i < 4; i++) a[i] = *(const float4*)&Qs[(4*w+i)*36 + k4];
#pragma unroll
                for (int j = 0; j < 2; j++) b[j] = *(const float4*)&Ks[(2*lane+j)*36 + k4];
#pragma unroll
                for (int i = 0; i < 4; i++)
#pragma unroll
                    for (int j = 0; j < 2; j++)
                        s[i][j] += a[i].x*b[j].x + a[i].y*b[j].y + a[i].z*b[j].z + a[i].w*b[j].w;
            }
#pragma unroll
            for (int i = 0; i < 4; i++)
#pragma unroll
                for (int j = 0; j < 2; j++)
                    Ss[(4*w+i)*65 + 2*lane + j] = s[i][j];
        }
        __syncthreads();
        // online softmax (warp 0: one lane per row)
        if (w == 0) {
            int r = lane;
            float mold = rmax[r];
            float m = mold;
#pragma unroll 8
            for (int j = 0; j < TK; j++) m = fmaxf(m, Ss[r*65 + j]);
            float ssum = 0.f;
#pragma unroll 8
            for (int j = 0; j < TK; j++) {
                float p = __expf(Ss[r*65 + j] - m);
                Ss[r*65 + j] = p;
                ssum += p;
            }
            float alf = __expf(mold - m);
            rsum[r] = rsum[r]*alf + ssum;
            rmax[r] = m;
            ralf[r] = alf;
        }
        __syncthreads();
        // rescale + P@V   (rows 4w+i, cols lane+32c)
#pragma unroll
        for (int i = 0; i < 4; i++) {
            float al = ralf[4*w+i];
#pragma unroll
            for (int c = 0; c < 4; c++) acc[i][c] *= al;
        }
#pragma unroll 4
        for (int jj = 0; jj < TK; jj++) {
            float p[4], vv[4];
#pragma unroll
            for (int i = 0; i < 4; i++) p[i] = Ss[(4*w+i)*65 + jj];
#pragma unroll
            for (int c = 0; c < 4; c++) vv[c] = Vs[jj*128 + lane + 32*c];
#pragma unroll
            for (int i = 0; i < 4; i++)
#pragma unroll
                for (int c = 0; c < 4; c++) acc[i][c] += p[i]*vv[c];
        }
    }
    // write normalized outputs
#pragma unroll
    for (int i = 0; i < 4; i++) {
        int r = qbase + 4*w + i;
        float inv = 1.0f / rsum[4*w + i];
        d_outv[r*EE + hoff + lane] = acc[i][0]*inv;
#pragma unroll
        for (int c = 1; c < 4; c++)
            d_outg[(r*NV + (c-1))*EE + hoff + lane] = acc[i][c]*inv;
    }
}

// ---------------- equ_out = gnew @ W_gdec  ([*,256]@[256,16]) ------------------
__global__ void gdec_kernel(const float* __restrict__ W_gdec, float* __restrict__ out)
{
    __shared__ float gs[16][EE];
    int rbase = blockIdx.x * 16;
    int t = threadIdx.x;
    for (int idx = t; idx < 16*EE; idx += 256)
        gs[idx >> 8][idx & 255] = d_gnew[(rbase + (idx >> 8))*EE + (idx & 255)];
    __syncthreads();
    int lr = t >> 4, c = t & 15;
    float acc = 0.f;
#pragma unroll 4
    for (int k2 = 0; k2 < EE; k2++) acc += gs[lr][k2] * W_gdec[k2*MM + c];
    out[(rbase + lr)*MM + c] = acc;
}

// ------------------------------------------------------------------------------
extern "C" void kernel_launch(void* const* d_in, const int* in_sizes, int n_in,
                              void* d_out, int out_size)
{
    const float* equ    = (const float*)d_in[0];
    const float* h      = (const float*)d_in[1];
    // d_in[2] edge_index, d_in[3] edge_fea: unused
    const float* W_equ  = (const float*)d_in[4];
    const float* W_gproj= (const float*)d_in[5];
    const float* W_vg   = (const float*)d_in[6];
    const float* W_g1   = (const float*)d_in[7];
    const float* b_g1   = (const float*)d_in[8];
    const float* W_g2   = (const float*)d_in[9];
    const float* b_g2   = (const float*)d_in[10];
    const float* W_q    = (const float*)d_in[11];
    const float* b_q    = (const float*)d_in[12];
    const float* W_k    = (const float*)d_in[13];
    const float* b_k    = (const float*)d_in[14];
    const float* W_v    = (const float*)d_in[15];
    const float* b_v    = (const float*)d_in[16];
    const float* W_ng   = (const float*)d_in[17];
    const float* b_ng   = (const float*)d_in[18];
    const float* W_gout = (const float*)d_in[19];
    const float* W_gdec = (const float*)d_in[20];
    const float* W_hdec = (const float*)d_in[21];
    const float* b_hdec = (const float*)d_in[22];
    float* out = (float*)d_out;

    float *g_src, *h2, *gram, *t1, *qb, *kb, *vb, *vgb, *outv, *outg, *hnew, *gnew;
    cudaGetSymbolAddress((void**)&g_src, d_g_src);
    cudaGetSymbolAddress((void**)&h2,    d_h2);
    cudaGetSymbolAddress((void**)&gram,  d_gram);
    cudaGetSymbolAddress((void**)&t1,    d_t1);
    cudaGetSymbolAddress((void**)&qb,    d_qb);
    cudaGetSymbolAddress((void**)&kb,    d_kb);
    cudaGetSymbolAddress((void**)&vb,    d_vb);
    cudaGetSymbolAddress((void**)&vgb,   d_vgb);
    cudaGetSymbolAddress((void**)&outv,  d_outv);
    cudaGetSymbolAddress((void**)&outg,  d_outg);
    cudaGetSymbolAddress((void**)&hnew,  d_hnew);
    cudaGetSymbolAddress((void**)&gnew,  d_gnew);

    // 1) prep
    gsrc_kernel<<<NR, 256>>>(equ, W_equ);
    hsrc_kernel<<<NN, 256>>>(h);
    gram_kernel<<<NN, 256>>>(W_gproj);

    // 2) MLP on gram:  t1 = relu(gram@W_g1+b),  g2 = t1@W_g2+b -> h2[:, :256]
    gemm_kernel<true, true, false><<<dim3(512/64, NN/64), 256>>>(
        gram, W_g1, b_g1, nullptr, t1, 1024, 512, 0, 512, 1.f);
    gemm_kernel<false, true, false><<<dim3(256/64, NN/64), 256>>>(
        t1, W_g2, b_g2, nullptr, h2, 512, 256, 0, 512, 1.f);

    // 3) q,k,v from h2;  vg from g_src
    gemm_kernel<false, true, false><<<dim3(256/64, NN/64), 256>>>(
        h2, W_q, b_q, nullptr, qb, 512, 256, 0, 256, SCALING);
    gemm_kernel<false, true, false><<<dim3(256/64, NN/64), 256>>>(
        h2, W_k, b_k, nullptr, kb, 512, 256, 0, 256, 1.f);
    gemm_kernel<false, true, false><<<dim3(256/64, NN/64), 256>>>(
        h2, W_v, b_v, nullptr, vb, 512, 256, 0, 256, 1.f);
    gemm_kernel<false, false, false><<<dim3(256/64, NR/64), 256>>>(
        g_src, W_vg, nullptr, nullptr, vgb, 256, 256, 0, 256, 1.f);

    // 4) fused flash attention over combined 128-wide value
    cudaFuncSetAttribute(attn_kernel, cudaFuncAttributeMaxDynamicSharedMemorySize,
                         ATTN_SMEM_BYTES);
    attn_kernel<<<dim3(NN/TQ, HH), 256, ATTN_SMEM_BYTES>>>(qb, kb, vb, vgb);

    // 5) h path:  hnew = h_src + outv@W_ng + b_ng ; h_out = hnew@W_hdec + b_hdec
    gemm_kernel<false, true, true><<<dim3(256/64, NN/64), 256>>>(
        outv, W_ng, b_ng, h2 + 256, hnew, 256, 256, 512, 256, 1.f);
    gemm_kernel<false, true, false><<<dim3(256/64, NN/64), 256>>>(
        hnew, W_hdec, b_hdec, nullptr, out + NR*MM, 256, 256, 0, 256, 1.f);

    // 6) g path:  gnew = g_src + outg@W_gout ;  equ_out = gnew@W_gdec
    gemm_kernel<false, false, true><<<dim3(256/64, NR/64), 256>>>(
        outg, W_gout, nullptr, g_src, gnew, 256, 256, 256, 256, 1.f);
    gdec_kernel<<<NR/16, 256>>>(W_gdec, out);
}

// round 4
// speedup vs baseline: 1.6984x; 1.6984x over previous
#include <cuda_runtime.h>
#include <cuda_bf16.h>
#include <math.h>
#include <stdint.h>

// Shapes (fixed for this problem)
#define NN   4096
#define NV   3
#define MM   16
#define EE   256
#define HH   8
#define DD   32
#define NR   (NN*NV)          // 12288 rows of g_src
#define SQRT_E 16.0f
#define SCALING 0.17677669529663687f   // 32^-0.5

// ---------------- scratch (device globals; no allocation allowed) -------------
__device__ float d_g_src[NR*EE];       // [N,n,E] scaled
__device__ float d_h2[NN*2*EE];        // [N, 512] = [g2 | h_src]
__device__ float d_gram[NN*1024];      // [N, 32*32]
__device__ float d_t1[NN*512];         // relu(gram@W_g1+b)
__device__ float d_qb[NN*EE];
__device__ float d_kb[NN*EE];
__device__ float d_vb[NN*EE];
__device__ float d_vgb[NR*EE];
__device__ float d_outv[NN*EE];
__device__ float d_outg[NR*EE];
__device__ float d_hnew[NN*EE];
__device__ float d_gnew[NR*EE];

// ---------------- helpers ------------------------------------------------------
__device__ __forceinline__ uint32_t f2tf(float x) {
    uint32_t r;
    asm("cvt.rna.tf32.f32 %0, %1;" : "=r"(r) : "f"(x));
    return r;
}
__device__ __forceinline__ uint32_t fu(float x) { return __float_as_uint(x); }

__device__ __forceinline__ void mma_tf32(float c[4],
    uint32_t a0, uint32_t a1, uint32_t a2, uint32_t a3,
    uint32_t b0, uint32_t b1)
{
    asm volatile(
        "mma.sync.aligned.m16n8k8.row.col.f32.tf32.tf32.f32 "
        "{%0,%1,%2,%3}, {%4,%5,%6,%7}, {%8,%9}, {%0,%1,%2,%3};\n"
        : "+f"(c[0]), "+f"(c[1]), "+f"(c[2]), "+f"(c[3])
        : "r"(a0), "r"(a1), "r"(a2), "r"(a3), "r"(b0), "r"(b1));
}

// fast e^x via FMA-only path (no MUFU). Accurate to ~2e-6 rel on useful range.
__device__ __forceinline__ float fexp(float x) {
    float y = x * 1.4426950408889634f;
    y = fmaxf(y, -126.0f);
    float n = rintf(y);
    float f = y - n;
    float p = 1.3333558146e-3f;
    p = fmaf(p, f, 9.6181291076e-3f);
    p = fmaf(p, f, 5.5504108665e-2f);
    p = fmaf(p, f, 2.4022650696e-1f);
    p = fmaf(p, f, 6.9314718056e-1f);
    p = fmaf(p, f, 1.0f);
    int e = (int)n;
    return p * __int_as_float((e + 127) << 23);
}

// ---------------- g_src = (equ @ W_equ) * 16 ----------------------------------
__global__ void gsrc_kernel(const float* __restrict__ equ,
                            const float* __restrict__ W_equ)
{
    __shared__ float es[MM];
    int r = blockIdx.x;
    int e = threadIdx.x;
    if (e < MM) es[e] = equ[r*MM + e];
    __syncthreads();
    float acc = 0.f;
#pragma unroll
    for (int m = 0; m < MM; m++) acc += es[m] * W_equ[m*EE + e];
    d_g_src[r*EE + e] = acc * SQRT_E;
}

// ---------------- h_src = h*16  (into h2[:,256:512]) --------------------------
__global__ void hsrc_kernel(const float* __restrict__ h)
{
    int i = blockIdx.x, e = threadIdx.x;
    d_h2[i*512 + 256 + e] = h[i*EE + e] * SQRT_E;
}

// ---------------- g2p + Gram ---------------------------------------------------
__global__ void gram_kernel(const float* __restrict__ W_gproj)
{
    __shared__ float gs[NV][EE];
    __shared__ float g2p[NV][32];
    int node = blockIdx.x;
    int t = threadIdx.x;
#pragma unroll
    for (int i = 0; i < NV; i++) gs[i][t] = d_g_src[(node*NV + i)*EE + t];
    __syncthreads();
    if (t < 96) {
        int i = t >> 5, a = t & 31;
        float acc = 0.f;
#pragma unroll 4
        for (int k2 = 0; k2 < EE; k2++) acc += gs[i][k2] * W_gproj[k2*32 + a];
        g2p[i][a] = acc;
    }
    __syncthreads();
#pragma unroll
    for (int o = t; o < 1024; o += 256) {
        int a = o >> 5, b = o & 31;
        float acc = g2p[0][a]*g2p[0][b] + g2p[1][a]*g2p[1][b] + g2p[2][a]*g2p[2][b];
        d_gram[node*1024 + o] = acc;
    }
}

// ---------------- generic tiled fp32 GEMM -------------------------------------
template<bool RELU, bool BIAS, bool RES>
__global__ __launch_bounds__(256)
void gemm_kernel(const float* __restrict__ A, const float* __restrict__ B,
                 const float* __restrict__ bias, const float* __restrict__ resid,
                 float* __restrict__ C, int K, int Nn,
                 int ldr, int ldc, float alpha)
{
    __shared__ float As[16][64];
    __shared__ float Bs[16][64];
    int tid = threadIdx.x;
    int tx = tid & 15, ty = tid >> 4;
    int m0 = blockIdx.y * 64, n0 = blockIdx.x * 64;
    int arow = tid >> 2;
    int acol = (tid & 3) * 4;
    int brow = tid >> 4;
    int bcol = (tid & 15) * 4;
    float acc[4][4] = {};

    for (int k0 = 0; k0 < K; k0 += 16) {
        float4 a4 = *(const float4*)&A[(m0 + arow)*K + k0 + acol];
        float4 b4 = *(const float4*)&B[(k0 + brow)*Nn + n0 + bcol];
        __syncthreads();
        As[acol+0][arow] = a4.x; As[acol+1][arow] = a4.y;
        As[acol+2][arow] = a4.z; As[acol+3][arow] = a4.w;
        *(float4*)&Bs[brow][bcol] = b4;
        __syncthreads();
#pragma unroll
        for (int kk = 0; kk < 16; kk++) {
            float4 av = *(const float4*)&As[kk][ty*4];
            float4 bv = *(const float4*)&Bs[kk][tx*4];
            float ar[4] = {av.x, av.y, av.z, av.w};
            float br[4] = {bv.x, bv.y, bv.z, bv.w};
#pragma unroll
            for (int i = 0; i < 4; i++)
#pragma unroll
                for (int j = 0; j < 4; j++)
                    acc[i][j] += ar[i]*br[j];
        }
    }
#pragma unroll
    for (int i = 0; i < 4; i++) {
        int row = m0 + ty*4 + i;
        float4 o;
        float vals[4];
#pragma unroll
        for (int j = 0; j < 4; j++) {
            int col = n0 + tx*4 + j;
            float v = acc[i][j];
            if (BIAS) v += bias[col];
            v *= alpha;
            if (RES)  v += resid[row*ldr + col];
            if (RELU) v = fmaxf(v, 0.f);
            vals[j] = v;
        }
        o.x = vals[0]; o.y = vals[1]; o.z = vals[2]; o.w = vals[3];
        *(float4*)&C[row*ldc + n0 + tx*4] = o;
    }
}

// ---------------- tensor-core flash attention ---------------------------------
// TQ=64 queries x one head per block, TK=64 key tiles.
// S = QK^T in tf32x2 (3 mmas), softmax fp32 with FMA-exp, P@V in single tf32.
// Combined value width 128 = [v | vg0 | vg1 | vg2] per head.
#define TQ 64
#define TK 64
// smem: Khi[64][36] Klo[64][36] Vc[64][132] Ss[64][68] smax/ssum/salf[64]
#define AT_KHI 0
#define AT_KLO (64*36)
#define AT_VC  (2*64*36)
#define AT_SS  (2*64*36 + 64*132)
#define AT_MAX (AT_SS + 64*68)
#define AT_SUM (AT_MAX + 64)
#define AT_ALF (AT_SUM + 64)
#define ATTN_SMEM_FLOATS (AT_ALF + 64)
#define ATTN_SMEM_BYTES  (ATTN_SMEM_FLOATS*4)

__global__ __launch_bounds__(256, 2)
void attn_mma_kernel(const float* __restrict__ q, const float* __restrict__ k,
                     const float* __restrict__ v, const float* __restrict__ vg)
{
    extern __shared__ float sm[];
    float* Khi = sm + AT_KHI;
    float* Klo = sm + AT_KLO;
    float* Vc  = sm + AT_VC;
    float* Ss  = sm + AT_SS;
    float* smax= sm + AT_MAX;
    float* ssum= sm + AT_SUM;
    float* salf= sm + AT_ALF;

    int tid  = threadIdx.x;
    int lane = tid & 31;
    int w    = tid >> 5;
    int hh   = blockIdx.y;
    int hoff = hh * DD;
    int qbase = blockIdx.x * TQ;

    int rs = 16 * (w >> 1);        // S/out row base (within tile)
    int cs = 32 * (w & 1);         // S col base
    int co = 64 * (w & 1);         // PV out col base (of 128)

    // preload Q fragments (tf32 hi/lo), rows rs..rs+15, all 32 k
    uint32_t qh[4][4], ql[4][4];
    {
        int gr0 = qbase + rs + (lane >> 2);
#pragma unroll
        for (int kk = 0; kk < 4; kk++) {
            int kc = hoff + kk*8 + (lane & 3);
            float v00 = q[gr0*EE + kc];
            float v10 = q[(gr0+8)*EE + kc];
            float v01 = q[gr0*EE + kc + 4];
            float v11 = q[(gr0+8)*EE + kc + 4];
            qh[kk][0] = f2tf(v00); ql[kk][0] = f2tf(v00 - __uint_as_float(qh[kk][0]));
            qh[kk][1] = f2tf(v10); ql[kk][1] = f2tf(v10 - __uint_as_float(qh[kk][1]));
            qh[kk][2] = f2tf(v01); ql[kk][2] = f2tf(v01 - __uint_as_float(qh[kk][2]));
            qh[kk][3] = f2tf(v11); ql[kk][3] = f2tf(v11 - __uint_as_float(qh[kk][3]));
        }
    }
    if (tid < TQ) { smax[tid] = -1e30f; ssum[tid] = 0.f; }

    float o[8][4] = {};

    for (int kb = 0; kb < NN; kb += TK) {
        __syncthreads();
        // load K tile: 64x32, hi/lo split
#pragma unroll
        for (int l = 0; l < 2; l++) {
            int idx = tid + l*256;
            int row = idx >> 3, c4 = (idx & 7) * 4;
            float4 kv = *(const float4*)&k[(kb+row)*EE + hoff + c4];
            float4 hi4, lo4;
            hi4.x = __uint_as_float(f2tf(kv.x)); lo4.x = __uint_as_float(f2tf(kv.x - hi4.x));
            hi4.y = __uint_as_float(f2tf(kv.y)); lo4.y = __uint_as_float(f2tf(kv.y - hi4.y));
            hi4.z = __uint_as_float(f2tf(kv.z)); lo4.z = __uint_as_float(f2tf(kv.z - hi4.z));
            hi4.w = __uint_as_float(f2tf(kv.w)); lo4.w = __uint_as_float(f2tf(kv.w - hi4.w));
            *(float4*)&Khi[row*36 + c4] = hi4;
            *(float4*)&Klo[row*36 + c4] = lo4;
        }
        // load V combined tile: 64x128 (tf32-rounded)
#pragma unroll
        for (int l = 0; l < 8; l++) {
            int idx = tid + l*256;
            int row = idx >> 5;
            int c4  = (idx & 31) * 4;
            const float* src;
            if (c4 < 32) src = &v[(kb+row)*EE + hoff + c4];
            else {
                int iv = (c4 - 32) >> 5, dcol = (c4 - 32) & 31;
                src = &vg[((kb+row)*NV + iv)*EE + hoff + dcol];
            }
            float4 vv = *(const float4*)src;
            vv.x = __uint_as_float(f2tf(vv.x));
            vv.y = __uint_as_float(f2tf(vv.y));
            vv.z = __uint_as_float(f2tf(vv.z));
            vv.w = __uint_as_float(f2tf(vv.w));
            *(float4*)&Vc[row*132 + c4] = vv;
        }
        __syncthreads();

        // ---- S = Q K^T (tf32x2), warp chunk 16x32 ----
        float sc[4][4];
#pragma unroll
        for (int j = 0; j < 4; j++)
#pragma unroll
            for (int i = 0; i < 4; i++) sc[j][i] = 0.f;
#pragma unroll
        for (int kk = 0; kk < 4; kk++) {
#pragma unroll
            for (int j = 0; j < 4; j++) {
                int nrow = cs + j*8 + (lane >> 2);
                int kc   = kk*8 + (lane & 3);
                uint32_t bh0 = fu(Khi[nrow*36 + kc]);
                uint32_t bh1 = fu(Khi[nrow*36 + kc + 4]);
                uint32_t bl0 = fu(Klo[nrow*36 + kc]);
                uint32_t bl1 = fu(Klo[nrow*36 + kc + 4]);
                mma_tf32(sc[j], qh[kk][0], qh[kk][1], qh[kk][2], qh[kk][3], bh0, bh1);
                mma_tf32(sc[j], ql[kk][0], ql[kk][1], ql[kk][2], ql[kk][3], bh0, bh1);
                mma_tf32(sc[j], qh[kk][0], qh[kk][1], qh[kk][2], qh[kk][3], bl0, bl1);
            }
        }
        // write S chunk to smem
#pragma unroll
        for (int j = 0; j < 4; j++) {
            int c0 = cs + j*8 + 2*(lane & 3);
            int r0 = rs + (lane >> 2);
            *(float2*)&Ss[r0*68 + c0]     = make_float2(sc[j][0], sc[j][1]);
            *(float2*)&Ss[(r0+8)*68 + c0] = make_float2(sc[j][2], sc[j][3]);
        }
        __syncthreads();

        // ---- online softmax: 4 threads per row, 16 cols each ----
        {
            int r = tid >> 2, qx = tid & 3;
            float* prow = &Ss[r*68 + qx*16];
            float m = -1e30f;
#pragma unroll
            for (int i = 0; i < 16; i++) m = fmaxf(m, prow[i]);
            m = fmaxf(m, __shfl_xor_sync(0xffffffffu, m, 1));
            m = fmaxf(m, __shfl_xor_sync(0xffffffffu, m, 2));
            float mold = smax[r];
            m = fmaxf(m, mold);
            float ps = 0.f;
#pragma unroll
            for (int i = 0; i < 16; i++) {
                float p = fexp(prow[i] - m);
                float pr = __uint_as_float(f2tf(p));   // round to tf32: consistent with MMA
                prow[i] = pr;
                ps += pr;
            }
            ps += __shfl_xor_sync(0xffffffffu, ps, 1);
            ps += __shfl_xor_sync(0xffffffffu, ps, 2);
            if (qx == 0) {
                float alf = fexp(mold - m);
                ssum[r] = ssum[r]*alf + ps;
                smax[r] = m;
                salf[r] = alf;
            }
        }
        __syncthreads();

        // ---- rescale + P@V (single tf32), warp out chunk 16x64 ----
        {
            float a0s = salf[rs + (lane >> 2)];
            float a1s = salf[rs + 8 + (lane >> 2)];
#pragma unroll
            for (int j = 0; j < 8; j++) {
                o[j][0] *= a0s; o[j][1] *= a0s;
                o[j][2] *= a1s; o[j][3] *= a1s;
            }
        }
#pragma unroll
        for (int kk = 0; kk < 8; kk++) {
            int r0 = rs + (lane >> 2);
            int kc = kk*8 + (lane & 3);
            uint32_t a0 = fu(Ss[r0*68 + kc]);
            uint32_t a1 = fu(Ss[(r0+8)*68 + kc]);
            uint32_t a2 = fu(Ss[r0*68 + kc + 4]);
            uint32_t a3 = fu(Ss[(r0+8)*68 + kc + 4]);
#pragma unroll
            for (int j = 0; j < 8; j++) {
                int nc = co + j*8 + (lane >> 2);
                uint32_t b0 = fu(Vc[(kk*8 + (lane & 3))*132 + nc]);
                uint32_t b1 = fu(Vc[(kk*8 + 4 + (lane & 3))*132 + nc]);
                mma_tf32(o[j], a0, a1, a2, a3, b0, b1);
            }
        }
    }

    // ---- epilogue: normalize and scatter ----
    {
        int lr0 = rs + (lane >> 2);
        float inv0 = 1.0f / ssum[lr0];
        float inv1 = 1.0f / ssum[lr0 + 8];
        int gr0 = qbase + lr0;
        int gr1 = gr0 + 8;
#pragma unroll
        for (int j = 0; j < 8; j++) {
            int col = co + j*8 + 2*(lane & 3);
#pragma unroll
            for (int s = 0; s < 2; s++) {
                int c = col + s;
                float v0 = o[j][s]   * inv0;
                float v1 = o[j][2+s] * inv1;
                if (c < 32) {
                    d_outv[gr0*EE + hoff + c] = v0;
                    d_outv[gr1*EE + hoff + c] = v1;
                } else {
                    int iv = (c - 32) >> 5, dc = (c - 32) & 31;
                    d_outg[(gr0*NV + iv)*EE + hoff + dc] = v0;
                    d_outg[(gr1*NV + iv)*EE + hoff + dc] = v1;
                }
            }
        }
    }
}

// ---------------- equ_out = gnew @ W_gdec  ([*,256]@[256,16]) ------------------
__global__ void gdec_kernel(const float* __restrict__ W_gdec, float* __restrict__ out)
{
    __shared__ float gs[16][EE];
    int rbase = blockIdx.x * 16;
    int t = threadIdx.x;
    for (int idx = t; idx < 16*EE; idx += 256)
        gs[idx >> 8][idx & 255] = d_gnew[(rbase + (idx >> 8))*EE + (idx & 255)];
    __syncthreads();
    int lr = t >> 4, c = t & 15;
    float acc = 0.f;
#pragma unroll 4
    for (int k2 = 0; k2 < EE; k2++) acc += gs[lr][k2] * W_gdec[k2*MM + c];
    out[(rbase + lr)*MM + c] = acc;
}

// ------------------------------------------------------------------------------
extern "C" void kernel_launch(void* const* d_in, const int* in_sizes, int n_in,
                              void* d_out, int out_size)
{
    const float* equ    = (const float*)d_in[0];
    const float* h      = (const float*)d_in[1];
    const float* W_equ  = (const float*)d_in[4];
    const float* W_gproj= (const float*)d_in[5];
    const float* W_vg   = (const float*)d_in[6];
    const float* W_g1   = (const float*)d_in[7];
    const float* b_g1   = (const float*)d_in[8];
    const float* W_g2   = (const float*)d_in[9];
    const float* b_g2   = (const float*)d_in[10];
    const float* W_q    = (const float*)d_in[11];
    const float* b_q    = (const float*)d_in[12];
    const float* W_k    = (const float*)d_in[13];
    const float* b_k    = (const float*)d_in[14];
    const float* W_v    = (const float*)d_in[15];
    const float* b_v    = (const float*)d_in[16];
    const float* W_ng   = (const float*)d_in[17];
    const float* b_ng   = (const float*)d_in[18];
    const float* W_gout = (const float*)d_in[19];
    const float* W_gdec = (const float*)d_in[20];
    const float* W_hdec = (const float*)d_in[21];
    const float* b_hdec = (const float*)d_in[22];
    float* out = (float*)d_out;

    float *g_src, *h2, *gram, *t1, *qb, *kb, *vb, *vgb, *outv, *outg, *hnew, *gnew;
    cudaGetSymbolAddress((void**)&g_src, d_g_src);
    cudaGetSymbolAddress((void**)&h2,    d_h2);
    cudaGetSymbolAddress((void**)&gram,  d_gram);
    cudaGetSymbolAddress((void**)&t1,    d_t1);
    cudaGetSymbolAddress((void**)&qb,    d_qb);
    cudaGetSymbolAddress((void**)&kb,    d_kb);
    cudaGetSymbolAddress((void**)&vb,    d_vb);
    cudaGetSymbolAddress((void**)&vgb,   d_vgb);
    cudaGetSymbolAddress((void**)&outv,  d_outv);
    cudaGetSymbolAddress((void**)&outg,  d_outg);
    cudaGetSymbolAddress((void**)&hnew,  d_hnew);
    cudaGetSymbolAddress((void**)&gnew,  d_gnew);

    // 1) prep
    gsrc_kernel<<<NR, 256>>>(equ, W_equ);
    hsrc_kernel<<<NN, 256>>>(h);
    gram_kernel<<<NN, 256>>>(W_gproj);

    // 2) MLP on gram
    gemm_kernel<true, true, false><<<dim3(512/64, NN/64), 256>>>(
        gram, W_g1, b_g1, nullptr, t1, 1024, 512, 0, 512, 1.f);
    gemm_kernel<false, true, false><<<dim3(256/64, NN/64), 256>>>(
        t1, W_g2, b_g2, nullptr, h2, 512, 256, 0, 512, 1.f);

    // 3) q,k,v from h2;  vg from g_src
    gemm_kernel<false, true, false><<<dim3(256/64, NN/64), 256>>>(
        h2, W_q, b_q, nullptr, qb, 512, 256, 0, 256, SCALING);
    gemm_kernel<false, true, false><<<dim3(256/64, NN/64), 256>>>(
        h2, W_k, b_k, nullptr, kb, 512, 256, 0, 256, 1.f);
    gemm_kernel<false, true, false><<<dim3(256/64, NN/64), 256>>>(
        h2, W_v, b_v, nullptr, vb, 512, 256, 0, 256, 1.f);
    gemm_kernel<false, false, false><<<dim3(256/64, NR/64), 256>>>(
        g_src, W_vg, nullptr, nullptr, vgb, 256, 256, 0, 256, 1.f);

    // 4) tensor-core flash attention
    cudaFuncSetAttribute(attn_mma_kernel, cudaFuncAttributeMaxDynamicSharedMemorySize,
                         ATTN_SMEM_BYTES);
    attn_mma_kernel<<<dim3(NN/TQ, HH), 256, ATTN_SMEM_BYTES>>>(qb, kb, vb, vgb);

    // 5) h path
    gemm_kernel<false, true, true><<<dim3(256/64, NN/64), 256>>>(
        outv, W_ng, b_ng, h2 + 256, hnew, 256, 256, 512, 256, 1.f);
    gemm_kernel<false, true, false><<<dim3(256/64, NN/64), 256>>>(
        hnew, W_hdec, b_hdec, nullptr, out + NR*MM, 256, 256, 0, 256, 1.f);

    // 6) g path
    gemm_kernel<false, false, true><<<dim3(256/64, NR/64), 256>>>(
        outg, W_gout, nullptr, g_src, gnew, 256, 256, 256, 256, 1.f);
    gdec_kernel<<<NR/16, 256>>>(W_gdec, out);
}

// round 5
// speedup vs baseline: 2.0148x; 1.1863x over previous
#include <cuda_runtime.h>
#include <cuda_bf16.h>
#include <math.h>
#include <stdint.h>

// Shapes (fixed for this problem)
#define NN   4096
#define NV   3
#define MM   16
#define EE   256
#define HH   8
#define DD   32
#define NR   (NN*NV)
#define SQRT_E 16.0f
#define SCALING 0.17677669529663687f   // 32^-0.5

// ---------------- scratch (device globals; no allocation allowed) -------------
__device__ float d_g_src[NR*EE];
__device__ float d_h2[NN*2*EE];        // [N, 512] = [g2 | h_src]
__device__ float d_gram[NN*1024];
__device__ float d_t1[NN*512];
__device__ float d_qb[NN*EE];
__device__ float d_kb[NN*EE];
__device__ float d_vb[NN*EE];
__device__ float d_vgb[NR*EE];
__device__ float d_outv[NN*EE];
__device__ float d_outg[NR*EE];
__device__ float d_hnew[NN*EE];
__device__ float d_gnew[NR*EE];

// ---------------- helpers ------------------------------------------------------
__device__ __forceinline__ uint32_t f2tf(float x) {
    uint32_t r;
    asm("cvt.rna.tf32.f32 %0, %1;" : "=r"(r) : "f"(x));
    return r;
}
__device__ __forceinline__ uint32_t fu(float x) { return __float_as_uint(x); }

__device__ __forceinline__ void mma_tf32(float c[4],
    uint32_t a0, uint32_t a1, uint32_t a2, uint32_t a3,
    uint32_t b0, uint32_t b1)
{
    asm volatile(
        "mma.sync.aligned.m16n8k8.row.col.f32.tf32.tf32.f32 "
        "{%0,%1,%2,%3}, {%4,%5,%6,%7}, {%8,%9}, {%0,%1,%2,%3};\n"
        : "+f"(c[0]), "+f"(c[1]), "+f"(c[2]), "+f"(c[3])
        : "r"(a0), "r"(a1), "r"(a2), "r"(a3), "r"(b0), "r"(b1));
}

// fast e^x via FMA-only path (no MUFU).
__device__ __forceinline__ float fexp(float x) {
    float y = x * 1.4426950408889634f;
    y = fmaxf(y, -126.0f);
    float n = rintf(y);
    float f = y - n;
    float p = 1.3333558146e-3f;
    p = fmaf(p, f, 9.6181291076e-3f);
    p = fmaf(p, f, 5.5504108665e-2f);
    p = fmaf(p, f, 2.4022650696e-1f);
    p = fmaf(p, f, 6.9314718056e-1f);
    p = fmaf(p, f, 1.0f);
    int e = (int)n;
    return p * __int_as_float((e + 127) << 23);
}

// ---------------- g_src = (equ @ W_equ) * 16 ----------------------------------
__global__ void gsrc_kernel(const float* __restrict__ equ,
                            const float* __restrict__ W_equ)
{
    __shared__ float es[MM];
    int r = blockIdx.x;
    int e = threadIdx.x;
    if (e < MM) es[e] = equ[r*MM + e];
    __syncthreads();
    float acc = 0.f;
#pragma unroll
    for (int m = 0; m < MM; m++) acc += es[m] * W_equ[m*EE + e];
    d_g_src[r*EE + e] = acc * SQRT_E;
}

// ---------------- h_src = h*16  (into h2[:,256:512]) --------------------------
__global__ void hsrc_kernel(const float* __restrict__ h)
{
    int i = blockIdx.x, e = threadIdx.x;
    d_h2[i*512 + 256 + e] = h[i*EE + e] * SQRT_E;
}

// ---------------- g2p + Gram ---------------------------------------------------
__global__ void gram_kernel(const float* __restrict__ W_gproj)
{
    __shared__ float gs[NV][EE];
    __shared__ float g2p[NV][32];
    int node = blockIdx.x;
    int t = threadIdx.x;
#pragma unroll
    for (int i = 0; i < NV; i++) gs[i][t] = d_g_src[(node*NV + i)*EE + t];
    __syncthreads();
    if (t < 96) {
        int i = t >> 5, a = t & 31;
        float acc = 0.f;
#pragma unroll 4
        for (int k2 = 0; k2 < EE; k2++) acc += gs[i][k2] * W_gproj[k2*32 + a];
        g2p[i][a] = acc;
    }
    __syncthreads();
#pragma unroll
    for (int o = t; o < 1024; o += 256) {
        int a = o >> 5, b = o & 31;
        float acc = g2p[0][a]*g2p[0][b] + g2p[1][a]*g2p[1][b] + g2p[2][a]*g2p[2][b];
        d_gram[node*1024 + o] = acc;
    }
}

// ---------------- tensor-core tf32 GEMM ----------------------------------------
// C[row*ldc+col] = post( alpha*(A@B + bias) + resid[row*ldr+col] )
// A row-major [M,K] (lda=K), B row-major [K,Nn]. 64x64 tile, K-chunk 32.
// X2: tf32 hi/lo compensated (3 mma) for logit-critical GEMMs.
template<bool RELU, bool BIAS, bool RES, bool X2>
__global__ __launch_bounds__(256)
void gemm_tc(const float* __restrict__ A, const float* __restrict__ B,
             const float* __restrict__ bias, const float* __restrict__ resid,
             float* __restrict__ C, int K, int Nn,
             int ldr, int ldc, float alpha)
{
    __shared__ float Ahi[64][36];
    __shared__ float Alo[64][36];
    __shared__ float Bhi[32][72];
    __shared__ float Blo[32][72];

    int tid = threadIdx.x, lane = tid & 31, w = tid >> 5;
    int m0 = blockIdx.y * 64, n0 = blockIdx.x * 64;
    int rs = 16 * (w >> 1);   // warp row base (0,16,32,48)
    int cs = 32 * (w & 1);    // warp col base (0,32)

    float acc[4][4] = {};

    for (int k0 = 0; k0 < K; k0 += 32) {
        __syncthreads();
        // A tile 64x32 -> hi/lo
        {
            int row = tid >> 3, c4 = (tid & 7) * 4;
#pragma unroll
            for (int l = 0; l < 2; l++) {
                int r = row + l*32;
                float4 a = *(const float4*)&A[(m0 + r)*K + k0 + c4];
                float4 hi;
                hi.x = __uint_as_float(f2tf(a.x));
                hi.y = __uint_as_float(f2tf(a.y));
                hi.z = __uint_as_float(f2tf(a.z));
                hi.w = __uint_as_float(f2tf(a.w));
                *(float4*)&Ahi[r][c4] = hi;
                if (X2) {
                    float4 lo;
                    lo.x = __uint_as_float(f2tf(a.x - hi.x));
                    lo.y = __uint_as_float(f2tf(a.y - hi.y));
                    lo.z = __uint_as_float(f2tf(a.z - hi.z));
                    lo.w = __uint_as_float(f2tf(a.w - hi.w));
                    *(float4*)&Alo[r][c4] = lo;
                }
            }
        }
        // B tile 32x64 -> hi/lo
        {
            int row = tid >> 4, c4 = (tid & 15) * 4;
#pragma unroll
            for (int l = 0; l < 2; l++) {
                int r = row + l*16;
                float4 b = *(const float4*)&B[(k0 + r)*Nn + n0 + c4];
                float4 hi;
                hi.x = __uint_as_float(f2tf(b.x));
                hi.y = __uint_as_float(f2tf(b.y));
                hi.z = __uint_as_float(f2tf(b.z));
                hi.w = __uint_as_float(f2tf(b.w));
                *(float4*)&Bhi[r][c4] = hi;
                if (X2) {
                    float4 lo;
                    lo.x = __uint_as_float(f2tf(b.x - hi.x));
                    lo.y = __uint_as_float(f2tf(b.y - hi.y));
                    lo.z = __uint_as_float(f2tf(b.z - hi.z));
                    lo.w = __uint_as_float(f2tf(b.w - hi.w));
                    *(float4*)&Blo[r][c4] = lo;
                }
            }
        }
        __syncthreads();

#pragma unroll
        for (int kk = 0; kk < 4; kk++) {
            int ar = rs + (lane >> 2);
            int kc = kk*8 + (lane & 3);
            uint32_t ah0 = fu(Ahi[ar][kc]);
            uint32_t ah1 = fu(Ahi[ar+8][kc]);
            uint32_t ah2 = fu(Ahi[ar][kc+4]);
            uint32_t ah3 = fu(Ahi[ar+8][kc+4]);
            uint32_t al0, al1, al2, al3;
            if (X2) {
                al0 = fu(Alo[ar][kc]);
                al1 = fu(Alo[ar+8][kc]);
                al2 = fu(Alo[ar][kc+4]);
                al3 = fu(Alo[ar+8][kc+4]);
            }
#pragma unroll
            for (int j = 0; j < 4; j++) {
                int nc = cs + j*8 + (lane >> 2);
                uint32_t bh0 = fu(Bhi[kc][nc]);          // kc row = kk*8+(lane&3)
                uint32_t bh1 = fu(Bhi[kk*8+4+(lane&3)][nc]);
                mma_tf32(acc[j], ah0, ah1, ah2, ah3, bh0, bh1);
                if (X2) {
                    uint32_t bl0 = fu(Blo[kk*8+(lane&3)][nc]);
                    uint32_t bl1 = fu(Blo[kk*8+4+(lane&3)][nc]);
                    mma_tf32(acc[j], al0, al1, al2, al3, bh0, bh1);
                    mma_tf32(acc[j], ah0, ah1, ah2, ah3, bl0, bl1);
                }
            }
        }
    }

    // epilogue
    int r0 = m0 + rs + (lane >> 2);
#pragma unroll
    for (int j = 0; j < 4; j++) {
        int col = n0 + cs + j*8 + 2*(lane & 3);
        float b0 = 0.f, b1 = 0.f;
        if (BIAS) { b0 = bias[col]; b1 = bias[col+1]; }
#pragma unroll
        for (int h2r = 0; h2r < 2; h2r++) {
            int row = r0 + h2r*8;
            float v0 = acc[j][2*h2r+0];
            float v1 = acc[j][2*h2r+1];
            if (BIAS) { v0 += b0; v1 += b1; }
            v0 *= alpha; v1 *= alpha;
            if (RES) {
                v0 += resid[row*ldr + col];
                v1 += resid[row*ldr + col + 1];
            }
            if (RELU) { v0 = fmaxf(v0, 0.f); v1 = fmaxf(v1, 0.f); }
            *(float2*)&C[row*ldc + col] = make_float2(v0, v1);
        }
    }
}

// ---------------- tensor-core flash attention (unchanged from R4) -------------
#define TQ 64
#define TK 64
#define AT_KHI 0
#define AT_KLO (64*36)
#define AT_VC  (2*64*36)
#define AT_SS  (2*64*36 + 64*132)
#define AT_MAX (AT_SS + 64*68)
#define AT_SUM (AT_MAX + 64)
#define AT_ALF (AT_SUM + 64)
#define ATTN_SMEM_FLOATS (AT_ALF + 64)
#define ATTN_SMEM_BYTES  (ATTN_SMEM_FLOATS*4)

__global__ __launch_bounds__(256, 2)
void attn_mma_kernel(const float* __restrict__ q, const float* __restrict__ k,
                     const float* __restrict__ v, const float* __restrict__ vg)
{
    extern __shared__ float sm[];
    float* Khi = sm + AT_KHI;
    float* Klo = sm + AT_KLO;
    float* Vc  = sm + AT_VC;
    float* Ss  = sm + AT_SS;
    float* smax= sm + AT_MAX;
    float* ssum= sm + AT_SUM;
    float* salf= sm + AT_ALF;

    int tid  = threadIdx.x;
    int lane = tid & 31;
    int w    = tid >> 5;
    int hh   = blockIdx.y;
    int hoff = hh * DD;
    int qbase = blockIdx.x * TQ;

    int rs = 16 * (w >> 1);
    int cs = 32 * (w & 1);
    int co = 64 * (w & 1);

    uint32_t qh[4][4], ql[4][4];
    {
        int gr0 = qbase + rs + (lane >> 2);
#pragma unroll
        for (int kk = 0; kk < 4; kk++) {
            int kc = hoff + kk*8 + (lane & 3);
            float v00 = q[gr0*EE + kc];
            float v10 = q[(gr0+8)*EE + kc];
            float v01 = q[gr0*EE + kc + 4];
            float v11 = q[(gr0+8)*EE + kc + 4];
            qh[kk][0] = f2tf(v00); ql[kk][0] = f2tf(v00 - __uint_as_float(qh[kk][0]));
            qh[kk][1] = f2tf(v10); ql[kk][1] = f2tf(v10 - __uint_as_float(qh[kk][1]));
            qh[kk][2] = f2tf(v01); ql[kk][2] = f2tf(v01 - __uint_as_float(qh[kk][2]));
            qh[kk][3] = f2tf(v11); ql[kk][3] = f2tf(v11 - __uint_as_float(qh[kk][3]));
        }
    }
    if (tid < TQ) { smax[tid] = -1e30f; ssum[tid] = 0.f; }

    float o[8][4] = {};

    for (int kb = 0; kb < NN; kb += TK) {
        __syncthreads();
#pragma unroll
        for (int l = 0; l < 2; l++) {
            int idx = tid + l*256;
            int row = idx >> 3, c4 = (idx & 7) * 4;
            float4 kv = *(const float4*)&k[(kb+row)*EE + hoff + c4];
            float4 hi4, lo4;
            hi4.x = __uint_as_float(f2tf(kv.x)); lo4.x = __uint_as_float(f2tf(kv.x - hi4.x));
            hi4.y = __uint_as_float(f2tf(kv.y)); lo4.y = __uint_as_float(f2tf(kv.y - hi4.y));
            hi4.z = __uint_as_float(f2tf(kv.z)); lo4.z = __uint_as_float(f2tf(kv.z - hi4.z));
            hi4.w = __uint_as_float(f2tf(kv.w)); lo4.w = __uint_as_float(f2tf(kv.w - hi4.w));
            *(float4*)&Khi[row*36 + c4] = hi4;
            *(float4*)&Klo[row*36 + c4] = lo4;
        }
#pragma unroll
        for (int l = 0; l < 8; l++) {
            int idx = tid + l*256;
            int row = idx >> 5;
            int c4  = (idx & 31) * 4;
            const float* src;
            if (c4 < 32) src = &v[(kb+row)*EE + hoff + c4];
            else {
                int iv = (c4 - 32) >> 5, dcol = (c4 - 32) & 31;
                src = &vg[((kb+row)*NV + iv)*EE + hoff + dcol];
            }
            float4 vv = *(const float4*)src;
            vv.x = __uint_as_float(f2tf(vv.x));
            vv.y = __uint_as_float(f2tf(vv.y));
            vv.z = __uint_as_float(f2tf(vv.z));
            vv.w = __uint_as_float(f2tf(vv.w));
            *(float4*)&Vc[row*132 + c4] = vv;
        }
        __syncthreads();

        float sc[4][4];
#pragma unroll
        for (int j = 0; j < 4; j++)
#pragma unroll
            for (int i = 0; i < 4; i++) sc[j][i] = 0.f;
#pragma unroll
        for (int kk = 0; kk < 4; kk++) {
#pragma unroll
            for (int j = 0; j < 4; j++) {
                int nrow = cs + j*8 + (lane >> 2);
                int kc   = kk*8 + (lane & 3);
                uint32_t bh0 = fu(Khi[nrow*36 + kc]);
                uint32_t bh1 = fu(Khi[nrow*36 + kc + 4]);
                uint32_t bl0 = fu(Klo[nrow*36 + kc]);
                uint32_t bl1 = fu(Klo[nrow*36 + kc + 4]);
                mma_tf32(sc[j], qh[kk][0], qh[kk][1], qh[kk][2], qh[kk][3], bh0, bh1);
                mma_tf32(sc[j], ql[kk][0], ql[kk][1], ql[kk][2], ql[kk][3], bh0, bh1);
                mma_tf32(sc[j], qh[kk][0], qh[kk][1], qh[kk][2], qh[kk][3], bl0, bl1);
            }
        }
#pragma unroll
        for (int j = 0; j < 4; j++) {
            int c0 = cs + j*8 + 2*(lane & 3);
            int r0 = rs + (lane >> 2);
            *(float2*)&Ss[r0*68 + c0]     = make_float2(sc[j][0], sc[j][1]);
            *(float2*)&Ss[(r0+8)*68 + c0] = make_float2(sc[j][2], sc[j][3]);
        }
        __syncthreads();

        {
            int r = tid >> 2, qx = tid & 3;
            float* prow = &Ss[r*68 + qx*16];
            float m = -1e30f;
#pragma unroll
            for (int i = 0; i < 16; i++) m = fmaxf(m, prow[i]);
            m = fmaxf(m, __shfl_xor_sync(0xffffffffu, m, 1));
            m = fmaxf(m, __shfl_xor_sync(0xffffffffu, m, 2));
            float mold = smax[r];
            m = fmaxf(m, mold);
            float ps = 0.f;
#pragma unroll
            for (int i = 0; i < 16; i++) {
                float p = fexp(prow[i] - m);
                float pr = __uint_as_float(f2tf(p));
                prow[i] = pr;
                ps += pr;
            }
            ps += __shfl_xor_sync(0xffffffffu, ps, 1);
            ps += __shfl_xor_sync(0xffffffffu, ps, 2);
            if (qx == 0) {
                float alf = fexp(mold - m);
                ssum[r] = ssum[r]*alf + ps;
                smax[r] = m;
                salf[r] = alf;
            }
        }
        __syncthreads();

        {
            float a0s = salf[rs + (lane >> 2)];
            float a1s = salf[rs + 8 + (lane >> 2)];
#pragma unroll
            for (int j = 0; j < 8; j++) {
                o[j][0] *= a0s; o[j][1] *= a0s;
                o[j][2] *= a1s; o[j][3] *= a1s;
            }
        }
#pragma unroll
        for (int kk = 0; kk < 8; kk++) {
            int r0 = rs + (lane >> 2);
            int kc = kk*8 + (lane & 3);
            uint32_t a0 = fu(Ss[r0*68 + kc]);
            uint32_t a1 = fu(Ss[(r0+8)*68 + kc]);
            uint32_t a2 = fu(Ss[r0*68 + kc + 4]);
            uint32_t a3 = fu(Ss[(r0+8)*68 + kc + 4]);
#pragma unroll
            for (int j = 0; j < 8; j++) {
                int nc = co + j*8 + (lane >> 2);
                uint32_t b0 = fu(Vc[(kk*8 + (lane & 3))*132 + nc]);
                uint32_t b1 = fu(Vc[(kk*8 + 4 + (lane & 3))*132 + nc]);
                mma_tf32(o[j], a0, a1, a2, a3, b0, b1);
            }
        }
    }

    {
        int lr0 = rs + (lane >> 2);
        float inv0 = 1.0f / ssum[lr0];
        float inv1 = 1.0f / ssum[lr0 + 8];
        int gr0 = qbase + lr0;
        int gr1 = gr0 + 8;
#pragma unroll
        for (int j = 0; j < 8; j++) {
            int col = co + j*8 + 2*(lane & 3);
#pragma unroll
            for (int s = 0; s < 2; s++) {
                int c = col + s;
                float v0 = o[j][s]   * inv0;
                float v1 = o[j][2+s] * inv1;
                if (c < 32) {
                    d_outv[gr0*EE + hoff + c] = v0;
                    d_outv[gr1*EE + hoff + c] = v1;
                } else {
                    int iv = (c - 32) >> 5, dc = (c - 32) & 31;
                    d_outg[(gr0*NV + iv)*EE + hoff + dc] = v0;
                    d_outg[(gr1*NV + iv)*EE + hoff + dc] = v1;
                }
            }
        }
    }
}

// ---------------- equ_out = gnew @ W_gdec  ([*,256]@[256,16]) ------------------
__global__ void gdec_kernel(const float* __restrict__ W_gdec, float* __restrict__ out)
{
    __shared__ float gs[16][EE];
    int rbase = blockIdx.x * 16;
    int t = threadIdx.x;
    for (int idx = t; idx < 16*EE; idx += 256)
        gs[idx >> 8][idx & 255] = d_gnew[(rbase + (idx >> 8))*EE + (idx & 255)];
    __syncthreads();
    int lr = t >> 4, c = t & 15;
    float acc = 0.f;
#pragma unroll 4
    for (int k2 = 0; k2 < EE; k2++) acc += gs[lr][k2] * W_gdec[k2*MM + c];
    out[(rbase + lr)*MM + c] = acc;
}

// ------------------------------------------------------------------------------
extern "C" void kernel_launch(void* const* d_in, const int* in_sizes, int n_in,
                              void* d_out, int out_size)
{
    const float* equ    = (const float*)d_in[0];
    const float* h      = (const float*)d_in[1];
    const float* W_equ  = (const float*)d_in[4];
    const float* W_gproj= (const float*)d_in[5];
    const float* W_vg   = (const float*)d_in[6];
    const float* W_g1   = (const float*)d_in[7];
    const float* b_g1   = (const float*)d_in[8];
    const float* W_g2   = (const float*)d_in[9];
    const float* b_g2   = (const float*)d_in[10];
    const float* W_q    = (const float*)d_in[11];
    const float* b_q    = (const float*)d_in[12];
    const float* W_k    = (const float*)d_in[13];
    const float* b_k    = (const float*)d_in[14];
    const float* W_v    = (const float*)d_in[15];
    const float* b_v    = (const float*)d_in[16];
    const float* W_ng   = (const float*)d_in[17];
    const float* b_ng   = (const float*)d_in[18];
    const float* W_gout = (const float*)d_in[19];
    const float* W_gdec = (const float*)d_in[20];
    const float* W_hdec = (const float*)d_in[21];
    const float* b_hdec = (const float*)d_in[22];
    float* out = (float*)d_out;

    float *g_src, *h2, *gram, *t1, *qb, *kb, *vb, *vgb, *outv, *outg, *hnew, *gnew;
    cudaGetSymbolAddress((void**)&g_src, d_g_src);
    cudaGetSymbolAddress((void**)&h2,    d_h2);
    cudaGetSymbolAddress((void**)&gram,  d_gram);
    cudaGetSymbolAddress((void**)&t1,    d_t1);
    cudaGetSymbolAddress((void**)&qb,    d_qb);
    cudaGetSymbolAddress((void**)&kb,    d_kb);
    cudaGetSymbolAddress((void**)&vb,    d_vb);
    cudaGetSymbolAddress((void**)&vgb,   d_vgb);
    cudaGetSymbolAddress((void**)&outv,  d_outv);
    cudaGetSymbolAddress((void**)&outg,  d_outg);
    cudaGetSymbolAddress((void**)&hnew,  d_hnew);
    cudaGetSymbolAddress((void**)&gnew,  d_gnew);

    // 1) prep
    gsrc_kernel<<<NR, 256>>>(equ, W_equ);
    hsrc_kernel<<<NN, 256>>>(h);
    gram_kernel<<<NN, 256>>>(W_gproj);

    // 2) MLP on gram (logit-critical -> x2)
    gemm_tc<true, true, false, true><<<dim3(512/64, NN/64), 256>>>(
        gram, W_g1, b_g1, nullptr, t1, 1024, 512, 0, 512, 1.f);
    gemm_tc<false, true, false, true><<<dim3(256/64, NN/64), 256>>>(
        t1, W_g2, b_g2, nullptr, h2, 512, 256, 0, 512, 1.f);

    // 3) q,k (x2), v,vg (single)
    gemm_tc<false, true, false, true><<<dim3(256/64, NN/64), 256>>>(
        h2, W_q, b_q, nullptr, qb, 512, 256, 0, 256, SCALING);
    gemm_tc<false, true, false, true><<<dim3(256/64, NN/64), 256>>>(
        h2, W_k, b_k, nullptr, kb, 512, 256, 0, 256, 1.f);
    gemm_tc<false, true, false, false><<<dim3(256/64, NN/64), 256>>>(
        h2, W_v, b_v, nullptr, vb, 512, 256, 0, 256, 1.f);
    gemm_tc<false, false, false, false><<<dim3(256/64, NR/64), 256>>>(
        g_src, W_vg, nullptr, nullptr, vgb, 256, 256, 0, 256, 1.f);

    // 4) tensor-core flash attention
    cudaFuncSetAttribute(attn_mma_kernel, cudaFuncAttributeMaxDynamicSharedMemorySize,
                         ATTN_SMEM_BYTES);
    attn_mma_kernel<<<dim3(NN/TQ, HH), 256, ATTN_SMEM_BYTES>>>(qb, kb, vb, vgb);

    // 5) h path (single)
    gemm_tc<false, true, true, false><<<dim3(256/64, NN/64), 256>>>(
        outv, W_ng, b_ng, h2 + 256, hnew, 256, 256, 512, 256, 1.f);
    gemm_tc<false, true, false, false><<<dim3(256/64, NN/64), 256>>>(
        hnew, W_hdec, b_hdec, nullptr, out + NR*MM, 256, 256, 0, 256, 1.f);

    // 6) g path (single)
    gemm_tc<false, false, true, false><<<dim3(256/64, NR/64), 256>>>(
        outg, W_gout, nullptr, g_src, gnew, 256, 256, 256, 256, 1.f);
    gdec_kernel<<<NR/16, 256>>>(W_gdec, out);
}

// round 8
// speedup vs baseline: 2.7240x; 1.3520x over previous
#include <cuda_runtime.h>
#include <cuda_fp16.h>
#include <math.h>
#include <stdint.h>

// Shapes (fixed for this problem)
#define NN   4096
#define NV   3
#define MM   16
#define EE   256
#define HH   8
#define DD   32
#define NR   (NN*NV)
#define SQRT_E 16.0f
#define SCALING 0.17677669529663687f   // 32^-0.5

// ---------------- scratch (device globals; no allocation allowed) -------------
__device__ float d_g_src[NR*EE];
__device__ float d_h2[NN*2*EE];        // [N, 512] = [g2 | h_src]
__device__ float d_gram[NN*1024];
__device__ float d_t1[NN*512];
__device__ float d_qb[NN*EE];
__device__ float d_kb[NN*EE];
__device__ float d_vb[NN*EE];
__device__ float d_vgb[NR*EE];
__device__ float d_outv[NN*EE];
__device__ float d_outg[NR*EE];
__device__ float d_hnew[NN*EE];
__device__ float d_gnew[NR*EE];
// fp16-packed attention operands
__device__ uint32_t d_kh[NN*128];      // K hi, half2 words: [node][128]
__device__ uint32_t d_kl[NN*128];      // K lo
__device__ __half  d_vt[HH*128*NN];    // combined V transposed: [h][c=128][node]

// ---------------- helpers ------------------------------------------------------
__device__ __forceinline__ uint32_t packh2(__half a, __half b) {
    __half2 t = __halves2half2(a, b);
    return *reinterpret_cast<uint32_t*>(&t);
}
__device__ __forceinline__ uint32_t cvth(float a, float b) {
    __half2 t = __floats2half2_rn(a, b);
    return *reinterpret_cast<uint32_t*>(&t);
}
__device__ __forceinline__ void cvthl(float a, float b, uint32_t& hi, uint32_t& lo) {
    __half ha = __float2half_rn(a), hb = __float2half_rn(b);
    __half la = __float2half_rn(a - __half2float(ha));
    __half lb = __float2half_rn(b - __half2float(hb));
    hi = packh2(ha, hb);
    lo = packh2(la, lb);
}

__device__ __forceinline__ void mma_f16(float c[4],
    uint32_t a0, uint32_t a1, uint32_t a2, uint32_t a3,
    uint32_t b0, uint32_t b1)
{
    asm volatile(
        "mma.sync.aligned.m16n8k16.row.col.f32.f16.f16.f32 "
        "{%0,%1,%2,%3}, {%4,%5,%6,%7}, {%8,%9}, {%0,%1,%2,%3};\n"
        : "+f"(c[0]), "+f"(c[1]), "+f"(c[2]), "+f"(c[3])
        : "r"(a0), "r"(a1), "r"(a2), "r"(a3), "r"(b0), "r"(b1));
}

// fast e^x via FMA-only path (no MUFU).
__device__ __forceinline__ float fexp(float x) {
    float y = x * 1.4426950408889634f;
    y = fmaxf(y, -126.0f);
    float n = rintf(y);
    float f = y - n;
    float p = 1.3333558146e-3f;
    p = fmaf(p, f, 9.6181291076e-3f);
    p = fmaf(p, f, 5.5504108665e-2f);
    p = fmaf(p, f, 2.4022650696e-1f);
    p = fmaf(p, f, 6.9314718056e-1f);
    p = fmaf(p, f, 1.0f);
    int e = (int)n;
    return p * __int_as_float((e + 127) << 23);
}

// ---------------- g_src = (equ @ W_equ) * 16 ----------------------------------
__global__ void gsrc_kernel(const float* __restrict__ equ,
                            const float* __restrict__ W_equ)
{
    __shared__ float es[MM];
    int r = blockIdx.x;
    int e = threadIdx.x;
    if (e < MM) es[e] = equ[r*MM + e];
    __syncthreads();
    float acc = 0.f;
#pragma unroll
    for (int m = 0; m < MM; m++) acc += es[m] * W_equ[m*EE + e];
    d_g_src[r*EE + e] = acc * SQRT_E;
}

// ---------------- h_src = h*16  (into h2[:,256:512]) --------------------------
__global__ void hsrc_kernel(const float* __restrict__ h)
{
    int i = blockIdx.x, e = threadIdx.x;
    d_h2[i*512 + 256 + e] = h[i*EE + e] * SQRT_E;
}

// ---------------- g2p + Gram ---------------------------------------------------
__global__ void gram_kernel(const float* __restrict__ W_gproj)
{
    __shared__ float gs[NV][EE];
    __shared__ float g2p[NV][32];
    int node = blockIdx.x;
    int t = threadIdx.x;
#pragma unroll
    for (int i = 0; i < NV; i++) gs[i][t] = d_g_src[(node*NV + i)*EE + t];
    __syncthreads();
    if (t < 96) {
        int i = t >> 5, a = t & 31;
        float acc = 0.f;
#pragma unroll 4
        for (int k2 = 0; k2 < EE; k2++) acc += gs[i][k2] * W_gproj[k2*32 + a];
        g2p[i][a] = acc;
    }
    __syncthreads();
#pragma unroll
    for (int o = t; o < 1024; o += 256) {
        int a = o >> 5, b = o & 31;
        float acc = g2p[0][a]*g2p[0][b] + g2p[1][a]*g2p[1][b] + g2p[2][a]*g2p[2][b];
        d_gram[node*1024 + o] = acc;
    }
}

// ---------------- fp16 tensor-core GEMM ----------------------------------------
// C[row*ldc+col] = post( alpha*(A@B + bias) + resid[row*ldr+col] )
// A row-major [M,K], B row-major [K,Nn]. 64x64 tile, K-chunk 32, m16n8k16.
// X2: fp16 hi/lo compensated (3 mma) for logit-critical GEMMs.
template<bool RELU, bool BIAS, bool RES, bool X2>
__global__ __launch_bounds__(256)
void gemm16(const float* __restrict__ A, const float* __restrict__ B,
            const float* __restrict__ bias, const float* __restrict__ resid,
            float* __restrict__ C, int K, int Nn,
            int ldr, int ldc, float alpha)
{
    __shared__ uint32_t Ahi[64][20];   // [m][k half2], stride 20 -> conflict-free frags
    __shared__ uint32_t Alo[64][20];
    __shared__ uint32_t Bhi[64][20];   // TRANSPOSED: [n][k half2]
    __shared__ uint32_t Blo[64][20];

    int tid = threadIdx.x, lane = tid & 31, w = tid >> 5;
    int m0 = blockIdx.y * 64, n0 = blockIdx.x * 64;
    int rs = 16 * (w >> 1);
    int cs = 32 * (w & 1);

    int afr = tid >> 2;          // A fill: row 0..63
    int afq = tid & 3;           // A fill: k-group (8 floats)
    int bfn = tid & 63;          // B fill: col n 0..63
    int bfk = tid >> 6;          // B fill: k-group (8 floats)

    float acc[4][4] = {};

    for (int k0 = 0; k0 < K; k0 += 32) {
        __syncthreads();
        // A tile 64x32 -> half2 (hi[/lo])
        {
            const float4* ap = (const float4*)&A[(m0 + afr)*K + k0 + afq*8];
            float4 x = ap[0], y = ap[1];
            if (X2) {
                cvthl(x.x, x.y, Ahi[afr][afq*4+0], Alo[afr][afq*4+0]);
                cvthl(x.z, x.w, Ahi[afr][afq*4+1], Alo[afr][afq*4+1]);
                cvthl(y.x, y.y, Ahi[afr][afq*4+2], Alo[afr][afq*4+2]);
                cvthl(y.z, y.w, Ahi[afr][afq*4+3], Alo[afr][afq*4+3]);
            } else {
                Ahi[afr][afq*4+0] = cvth(x.x, x.y);
                Ahi[afr][afq*4+1] = cvth(x.z, x.w);
                Ahi[afr][afq*4+2] = cvth(y.x, y.y);
                Ahi[afr][afq*4+3] = cvth(y.z, y.w);
            }
        }
        // B tile 32x64 -> transposed half2
        {
            float v[8];
#pragma unroll
            for (int i = 0; i < 8; i++)
                v[i] = B[(k0 + bfk*8 + i)*Nn + n0 + bfn];
            if (X2) {
                cvthl(v[0], v[1], Bhi[bfn][bfk*4+0], Blo[bfn][bfk*4+0]);
                cvthl(v[2], v[3], Bhi[bfn][bfk*4+1], Blo[bfn][bfk*4+1]);
                cvthl(v[4], v[5], Bhi[bfn][bfk*4+2], Blo[bfn][bfk*4+2]);
                cvthl(v[6], v[7], Bhi[bfn][bfk*4+3], Blo[bfn][bfk*4+3]);
            } else {
                Bhi[bfn][bfk*4+0] = cvth(v[0], v[1]);
                Bhi[bfn][bfk*4+1] = cvth(v[2], v[3]);
                Bhi[bfn][bfk*4+2] = cvth(v[4], v[5]);
                Bhi[bfn][bfk*4+3] = cvth(v[6], v[7]);
            }
        }
        __syncthreads();

#pragma unroll
        for (int kk = 0; kk < 2; kk++) {
            int ar = rs + (lane >> 2);
            int ac = kk*8 + (lane & 3);
            uint32_t ah0 = Ahi[ar][ac],   ah1 = Ahi[ar+8][ac];
            uint32_t ah2 = Ahi[ar][ac+4], ah3 = Ahi[ar+8][ac+4];
            uint32_t al0, al1, al2, al3;
            if (X2) {
                al0 = Alo[ar][ac];   al1 = Alo[ar+8][ac];
                al2 = Alo[ar][ac+4]; al3 = Alo[ar+8][ac+4];
            }
#pragma unroll
            for (int j = 0; j < 4; j++) {
                int bn = cs + j*8 + (lane >> 2);
                uint32_t b0 = Bhi[bn][ac], b1 = Bhi[bn][ac+4];
                mma_f16(acc[j], ah0, ah1, ah2, ah3, b0, b1);
                if (X2) {
                    uint32_t bl0 = Blo[bn][ac], bl1 = Blo[bn][ac+4];
                    mma_f16(acc[j], al0, al1, al2, al3, b0, b1);
                    mma_f16(acc[j], ah0, ah1, ah2, ah3, bl0, bl1);
                }
            }
        }
    }

    // epilogue (C frag: c0,c1 at (r, 2q..2q+1); c2,c3 at r+8)
    int r0 = m0 + rs + (lane >> 2);
#pragma unroll
    for (int j = 0; j < 4; j++) {
        int col = n0 + cs + j*8 + 2*(lane & 3);
        float b0 = 0.f, b1 = 0.f;
        if (BIAS) { b0 = bias[col]; b1 = bias[col+1]; }
#pragma unroll
        for (int h2r = 0; h2r < 2; h2r++) {
            int row = r0 + h2r*8;
            float v0 = acc[j][2*h2r+0];
            float v1 = acc[j][2*h2r+1];
            if (BIAS) { v0 += b0; v1 += b1; }
            v0 *= alpha; v1 *= alpha;
            if (RES) {
                v0 += resid[row*ldr + col];
                v1 += resid[row*ldr + col + 1];
            }
            if (RELU) { v0 = fmaxf(v0, 0.f); v1 = fmaxf(v1, 0.f); }
            *(float2*)&C[row*ldc + col] = make_float2(v0, v1);
        }
    }
}

// ---------------- pack kernels -------------------------------------------------
// K -> fp16 hi/lo half2 words [node][128]
__global__ void pack_k_kernel()
{
    int idx = blockIdx.x * 256 + threadIdx.x;     // over NN*128
    float a = d_kb[idx*2], b = d_kb[idx*2+1];
    cvthl(a, b, d_kh[idx], d_kl[idx]);
}

// combined V transposed: d_vt[h][c][node], c: 0..31 = v head-dim, 32..127 = vg
__global__ void pack_v_kernel()
{
    int idx = blockIdx.x * 256 + threadIdx.x;     // over HH*128*NN
    int node = idx & (NN-1);
    int hc = idx >> 12;
    int h = hc >> 7, c = hc & 127;
    float s;
    if (c < 32) s = d_vb[node*EE + h*DD + c];
    else {
        int iv = (c - 32) >> 5, dc = (c - 32) & 31;
        s = d_vgb[(node*NV + iv)*EE + h*DD + dc];
    }
    d_vt[idx] = __float2half_rn(s);
}

// ---------------- fp16 tensor-core flash attention -----------------------------
// TQ=64 queries x one head per block, TK=64 key tiles.
// S = QK^T fp16 hi/lo (3 mma m16n8k16), softmax fp32 FMA-exp, P@V single fp16.
#define TQ 64
#define TK 64
// smem layout (bytes): KH 5120 | KL 5120 | VT 18432 | SS 17408 | PS 9216 | stats 768
#define ATTN_SMEM_BYTES (5120 + 5120 + 18432 + 17408 + 9216 + 768)

__global__ __launch_bounds__(256, 2)
void attn_f16_kernel(const float* __restrict__ q)
{
    extern __shared__ char smc[];
    uint32_t* KH = (uint32_t*)smc;                // [64][20] half2
    uint32_t* KL = KH + 64*20;                    // [64][20]
    uint32_t* VT = KL + 64*20;                    // [128][36] half2 (n-major, k contiguous)
    float*    SS = (float*)(VT + 128*36);         // [64][68] fp32 scores
    uint32_t* PS = (uint32_t*)(SS + 64*68);       // [64][36] half2 probs
    float*  rmax = (float*)(PS + 64*36);
    float*  rsum = rmax + 64;
    float*  ralf = rsum + 64;

    int tid  = threadIdx.x;
    int lane = tid & 31;
    int w    = tid >> 5;
    int hh   = blockIdx.y;
    int hoff = hh * DD;
    int qbase = blockIdx.x * TQ;

    int rs = 16 * (w >> 1);      // warp row base
    int cs = 32 * (w & 1);       // warp S-col base
    int co = 64 * (w & 1);       // warp PV out-col base

    // ---- preload Q fragments fp16 hi/lo (2 k16 chunks) ----
    uint32_t qh[2][4], ql[2][4];
    {
        int gr0 = qbase + rs + (lane >> 2);
#pragma unroll
        for (int kk = 0; kk < 2; kk++) {
            int c0 = hoff + kk*16 + 2*(lane & 3);
            float2 x0 = *(const float2*)&q[gr0*EE + c0];
            float2 x1 = *(const float2*)&q[(gr0+8)*EE + c0];
            float2 x2 = *(const float2*)&q[gr0*EE + c0 + 8];
            float2 x3 = *(const float2*)&q[(gr0+8)*EE + c0 + 8];
            cvthl(x0.x, x0.y, qh[kk][0], ql[kk][0]);
            cvthl(x1.x, x1.y, qh[kk][1], ql[kk][1]);
            cvthl(x2.x, x2.y, qh[kk][2], ql[kk][2]);
            cvthl(x3.x, x3.y, qh[kk][3], ql[kk][3]);
        }
    }
    if (tid < TQ) { rmax[tid] = -1e30f; rsum[tid] = 0.f; }

    float o[8][4] = {};

    for (int kb = 0; kb < NN; kb += TK) {
        __syncthreads();
        // ---- fill K tile from packed global (hi/lo) ----
#pragma unroll
        for (int l = 0; l < 2; l++) {
            int idx = tid + l*256;
            int row = idx >> 3, cp = (idx & 7) * 2;
            int g = (kb + row)*128 + hh*16 + cp;
            uint2 vh = *(const uint2*)&d_kh[g];
            uint2 vl = *(const uint2*)&d_kl[g];
            KH[row*20 + cp] = vh.x; KH[row*20 + cp + 1] = vh.y;
            KL[row*20 + cp] = vl.x; KL[row*20 + cp + 1] = vl.y;
        }
        // ---- fill V tile (transposed layout, contiguous in k) ----
#pragma unroll
        for (int l = 0; l < 4; l++) {
            int idx = tid + l*256;
            int row = idx >> 3;          // 0..127 (out col)
            int c16 = idx & 7;           // 8-half chunk
            uint4 vv = *(const uint4*)&d_vt[(hh*128 + row)*NN + kb + c16*8];
            *(uint4*)&VT[row*36 + c16*4] = vv;
        }
        __syncthreads();

        // ---- S = Q K^T (fp16 hi/lo), warp chunk 16x32 ----
        float sc[4][4];
#pragma unroll
        for (int j = 0; j < 4; j++)
#pragma unroll
            for (int i = 0; i < 4; i++) sc[j][i] = 0.f;
#pragma unroll
        for (int kk = 0; kk < 2; kk++) {
#pragma unroll
            for (int j = 0; j < 4; j++) {
                int nrow = cs + j*8 + (lane >> 2);
                int kc   = kk*8 + (lane & 3);
                uint32_t bh0 = KH[nrow*20 + kc], bh1 = KH[nrow*20 + kc + 4];
                uint32_t bl0 = KL[nrow*20 + kc], bl1 = KL[nrow*20 + kc + 4];
                mma_f16(sc[j], qh[kk][0], qh[kk][1], qh[kk][2], qh[kk][3], bh0, bh1);
                mma_f16(sc[j], ql[kk][0], ql[kk][1], ql[kk][2], ql[kk][3], bh0, bh1);
                mma_f16(sc[j], qh[kk][0], qh[kk][1], qh[kk][2], qh[kk][3], bl0, bl1);
            }
        }
#pragma unroll
        for (int j = 0; j < 4; j++) {
            int c0 = cs + j*8 + 2*(lane & 3);
            int r0 = rs + (lane >> 2);
            *(float2*)&SS[r0*68 + c0]     = make_float2(sc[j][0], sc[j][1]);
            *(float2*)&SS[(r0+8)*68 + c0] = make_float2(sc[j][2], sc[j][3]);
        }
        __syncthreads();

        // ---- online softmax: 4 threads per row, 16 cols each; P -> fp16 ----
        {
            int r = tid >> 2, qx = tid & 3;
            float* prow = &SS[r*68 + qx*16];
            float m = -1e30f;
#pragma unroll
            for (int i = 0; i < 16; i++) m = fmaxf(m, prow[i]);
            m = fmaxf(m, __shfl_xor_sync(0xffffffffu, m, 1));
            m = fmaxf(m, __shfl_xor_sync(0xffffffffu, m, 2));
            float mold = rmax[r];
            m = fmaxf(m, mold);
            float ps = 0.f;
#pragma unroll
            for (int i = 0; i < 8; i++) {
                float pa = fexp(prow[2*i]   - m);
                float pb = fexp(prow[2*i+1] - m);
                __half ha = __float2half_rn(pa);
                __half hb = __float2half_rn(pb);
                PS[r*36 + qx*8 + i] = packh2(ha, hb);
                ps += __half2float(ha) + __half2float(hb);
            }
            ps += __shfl_xor_sync(0xffffffffu, ps, 1);
            ps += __shfl_xor_sync(0xffffffffu, ps, 2);
            if (qx == 0) {
                float alf = fexp(mold - m);
                rsum[r] = rsum[r]*alf + ps;
                rmax[r] = m;
                ralf[r] = alf;
            }
        }
        __syncthreads();

        // ---- rescale + P@V (single fp16), warp out chunk 16x64 ----
        {
            float a0s = ralf[rs + (lane >> 2)];
            float a1s = ralf[rs + 8 + (lane >> 2)];
#pragma unroll
            for (int j = 0; j < 8; j++) {
                o[j][0] *= a0s; o[j][1] *= a0s;
                o[j][2] *= a1s; o[j][3] *= a1s;
            }
        }
#pragma unroll
        for (int kk = 0; kk < 4; kk++) {
            int r0 = rs + (lane >> 2);
            int ac = kk*8 + (lane & 3);
            uint32_t a0 = PS[r0*36 + ac];
            uint32_t a1 = PS[(r0+8)*36 + ac];
            uint32_t a2 = PS[r0*36 + ac + 4];
            uint32_t a3 = PS[(r0+8)*36 + ac + 4];
#pragma unroll
            for (int j = 0; j < 8; j++) {
                int nc = co + j*8 + (lane >> 2);
                uint32_t b0 = VT[nc*36 + ac], b1 = VT[nc*36 + ac + 4];
                mma_f16(o[j], a0, a1, a2, a3, b0, b1);
            }
        }
    }

    // ---- epilogue: normalize and scatter ----
    {
        int lr0 = rs + (lane >> 2);
        float inv0 = 1.0f / rsum[lr0];
        float inv1 = 1.0f / rsum[lr0 + 8];
        int gr0 = qbase + lr0;
        int gr1 = gr0 + 8;
#pragma unroll
        for (int j = 0; j < 8; j++) {
            int col = co + j*8 + 2*(lane & 3);
#pragma unroll
            for (int s = 0; s < 2; s++) {
                int c = col + s;
                float v0 = o[j][s]   * inv0;
                float v1 = o[j][2+s] * inv1;
                if (c < 32) {
                    d_outv[gr0*EE + hoff + c] = v0;
                    d_outv[gr1*EE + hoff + c] = v1;
                } else {
                    int iv = (c - 32) >> 5, dc = (c - 32) & 31;
                    d_outg[(gr0*NV + iv)*EE + hoff + dc] = v0;
                    d_outg[(gr1*NV + iv)*EE + hoff + dc] = v1;
                }
            }
        }
    }
}

// ---------------- equ_out = gnew @ W_gdec  ([*,256]@[256,16]) ------------------
__global__ void gdec_kernel(const float* __restrict__ W_gdec, float* __restrict__ out)
{
    __shared__ float gs[16][EE];
    int rbase = blockIdx.x * 16;
    int t = threadIdx.x;
    for (int idx = t; idx < 16*EE; idx += 256)
        gs[idx >> 8][idx & 255] = d_gnew[(rbase + (idx >> 8))*EE + (idx & 255)];
    __syncthreads();
    int lr = t >> 4, c = t & 15;
    float acc = 0.f;
#pragma unroll 4
    for (int k2 = 0; k2 < EE; k2++) acc += gs[lr][k2] * W_gdec[k2*MM + c];
    out[(rbase + lr)*MM + c] = acc;
}

// ------------------------------------------------------------------------------
extern "C" void kernel_launch(void* const* d_in, const int* in_sizes, int n_in,
                              void* d_out, int out_size)
{
    const float* equ    = (const float*)d_in[0];
    const float* h      = (const float*)d_in[1];
    const float* W_equ  = (const float*)d_in[4];
    const float* W_gproj= (const float*)d_in[5];
    const float* W_vg   = (const float*)d_in[6];
    const float* W_g1   = (const float*)d_in[7];
    const float* b_g1   = (const float*)d_in[8];
    const float* W_g2   = (const float*)d_in[9];
    const float* b_g2   = (const float*)d_in[10];
    const float* W_q    = (const float*)d_in[11];
    const float* b_q    = (const float*)d_in[12];
    const float* W_k    = (const float*)d_in[13];
    const float* b_k    = (const float*)d_in[14];
    const float* W_v    = (const float*)d_in[15];
    const float* b_v    = (const float*)d_in[16];
    const float* W_ng   = (const float*)d_in[17];
    const float* b_ng   = (const float*)d_in[18];
    const float* W_gout = (const float*)d_in[19];
    const float* W_gdec = (const float*)d_in[20];
    const float* W_hdec = (const float*)d_in[21];
    const float* b_hdec = (const float*)d_in[22];
    float* out = (float*)d_out;

    float *g_src, *h2, *gram, *t1, *qb, *kb, *vb, *vgb, *outv, *outg, *hnew, *gnew;
    cudaGetSymbolAddress((void**)&g_src, d_g_src);
    cudaGetSymbolAddress((void**)&h2,    d_h2);
    cudaGetSymbolAddress((void**)&gram,  d_gram);
    cudaGetSymbolAddress((void**)&t1,    d_t1);
    cudaGetSymbolAddress((void**)&qb,    d_qb);
    cudaGetSymbolAddress((void**)&kb,    d_kb);
    cudaGetSymbolAddress((void**)&vb,    d_vb);
    cudaGetSymbolAddress((void**)&vgb,   d_vgb);
    cudaGetSymbolAddress((void**)&outv,  d_outv);
    cudaGetSymbolAddress((void**)&outg,  d_outg);
    cudaGetSymbolAddress((void**)&hnew,  d_hnew);
    cudaGetSymbolAddress((void**)&gnew,  d_gnew);

    // 1) prep
    gsrc_kernel<<<NR, 256>>>(equ, W_equ);
    hsrc_kernel<<<NN, 256>>>(h);
    gram_kernel<<<NN, 256>>>(W_gproj);

    // 2) MLP on gram (logit-critical -> X2)
    gemm16<true, true, false, true><<<dim3(512/64, NN/64), 256>>>(
        gram, W_g1, b_g1, nullptr, t1, 1024, 512, 0, 512, 1.f);
    gemm16<false, true, false, true><<<dim3(256/64, NN/64), 256>>>(
        t1, W_g2, b_g2, nullptr, h2, 512, 256, 0, 512, 1.f);

    // 3) q,k (X2), v,vg (single)
    gemm16<false, true, false, true><<<dim3(256/64, NN/64), 256>>>(
        h2, W_q, b_q, nullptr, qb, 512, 256, 0, 256, SCALING);
    gemm16<false, true, false, true><<<dim3(256/64, NN/64), 256>>>(
        h2, W_k, b_k, nullptr, kb, 512, 256, 0, 256, 1.f);
    gemm16<false, true, false, false><<<dim3(256/64, NN/64), 256>>>(
        h2, W_v, b_v, nullptr, vb, 512, 256, 0, 256, 1.f);
    gemm16<false, false, false, false><<<dim3(256/64, NR/64), 256>>>(
        g_src, W_vg, nullptr, nullptr, vgb, 256, 256, 0, 256, 1.f);

    // 3b) pack K (hi/lo fp16) and combined V (fp16, transposed)
    pack_k_kernel<<<NN*128/256, 256>>>();
    pack_v_kernel<<<HH*128*NN/256, 256>>>();

    // 4) fp16 tensor-core flash attention
    cudaFuncSetAttribute(attn_f16_kernel, cudaFuncAttributeMaxDynamicSharedMemorySize,
                         ATTN_SMEM_BYTES);
    attn_f16_kernel<<<dim3(NN/TQ, HH), 256, ATTN_SMEM_BYTES>>>(qb);

    // 5) h path (single)
    gemm16<false, true, true, false><<<dim3(256/64, NN/64), 256>>>(
        outv, W_ng, b_ng, h2 + 256, hnew, 256, 256, 512, 256, 1.f);
    gemm16<false, true, false, false><<<dim3(256/64, NN/64), 256>>>(
        hnew, W_hdec, b_hdec, nullptr, out + NR*MM, 256, 256, 0, 256, 1.f);

    // 6) g path (single)
    gemm16<false, false, true, false><<<dim3(256/64, NR/64), 256>>>(
        outg, W_gout, nullptr, g_src, gnew, 256, 256, 256, 256, 1.f);
    gdec_kernel<<<NR/16, 256>>>(W_gdec, out);
}

// round 9
// speedup vs baseline: 3.1450x; 1.1546x over previous
#include <cuda_runtime.h>
#include <cuda_fp16.h>
#include <math.h>
#include <stdint.h>

// Shapes (fixed for this problem)
#define NN   4096
#define NV   3
#define MM   16
#define EE   256
#define HH   8
#define DD   32
#define NR   (NN*NV)
#define SQRT_E 16.0f
#define SCALING 0.17677669529663687f   // 32^-0.5

// ---------------- scratch (device globals; no allocation allowed) -------------
__device__ float d_g_src[NR*EE];
__device__ float d_h2[NN*2*EE];        // [N, 512] = [g2 | h_src]
__device__ float d_gram[NN*1024];
__device__ float d_t1[NN*512];
__device__ float d_qb[NN*EE];
__device__ float d_kb[NN*EE];
__device__ float d_vb[NN*EE];
__device__ float d_vgb[NR*EE];
__device__ float d_outv[NN*EE];
__device__ float d_outg[NR*EE];
__device__ float d_hnew[NN*EE];
__device__ float d_gnew[NR*EE];
// fp16-packed attention operands
__device__ uint32_t d_kh[NN*128];      // K hi, half2 words: [node][128]
__device__ uint32_t d_kl[NN*128];      // K lo
__device__ __half  d_vt[HH*128*NN];    // combined V transposed: [h][c=128][node]

// ---------------- helpers ------------------------------------------------------
__device__ __forceinline__ uint32_t packh2(__half a, __half b) {
    __half2 t = __halves2half2(a, b);
    return *reinterpret_cast<uint32_t*>(&t);
}
__device__ __forceinline__ uint32_t cvth(float a, float b) {
    __half2 t = __floats2half2_rn(a, b);
    return *reinterpret_cast<uint32_t*>(&t);
}
__device__ __forceinline__ void cvthl(float a, float b, uint32_t& hi, uint32_t& lo) {
    __half ha = __float2half_rn(a), hb = __float2half_rn(b);
    __half la = __float2half_rn(a - __half2float(ha));
    __half lb = __float2half_rn(b - __half2float(hb));
    hi = packh2(ha, hb);
    lo = packh2(la, lb);
}

__device__ __forceinline__ void mma_f16(float c[4],
    uint32_t a0, uint32_t a1, uint32_t a2, uint32_t a3,
    uint32_t b0, uint32_t b1)
{
    asm volatile(
        "mma.sync.aligned.m16n8k16.row.col.f32.f16.f16.f32 "
        "{%0,%1,%2,%3}, {%4,%5,%6,%7}, {%8,%9}, {%0,%1,%2,%3};\n"
        : "+f"(c[0]), "+f"(c[1]), "+f"(c[2]), "+f"(c[3])
        : "r"(a0), "r"(a1), "r"(a2), "r"(a3), "r"(b0), "r"(b1));
}

__device__ __forceinline__ void ldsm4(uint32_t& r0, uint32_t& r1,
                                      uint32_t& r2, uint32_t& r3, const void* p)
{
    uint32_t addr = (uint32_t)__cvta_generic_to_shared(p);
    asm volatile("ldmatrix.sync.aligned.m8n8.x4.shared.b16 {%0,%1,%2,%3}, [%4];"
                 : "=r"(r0), "=r"(r1), "=r"(r2), "=r"(r3) : "r"(addr));
}

// fast e^x via FMA-only path (no MUFU).
__device__ __forceinline__ float fexp(float x) {
    float y = x * 1.4426950408889634f;
    y = fmaxf(y, -126.0f);
    float n = rintf(y);
    float f = y - n;
    float p = 1.3333558146e-3f;
    p = fmaf(p, f, 9.6181291076e-3f);
    p = fmaf(p, f, 5.5504108665e-2f);
    p = fmaf(p, f, 2.4022650696e-1f);
    p = fmaf(p, f, 6.9314718056e-1f);
    p = fmaf(p, f, 1.0f);
    int e = (int)n;
    return p * __int_as_float((e + 127) << 23);
}

// ---------------- g_src = (equ @ W_equ) * 16 ----------------------------------
__global__ void gsrc_kernel(const float* __restrict__ equ,
                            const float* __restrict__ W_equ)
{
    __shared__ float es[MM];
    int r = blockIdx.x;
    int e = threadIdx.x;
    if (e < MM) es[e] = equ[r*MM + e];
    __syncthreads();
    float acc = 0.f;
#pragma unroll
    for (int m = 0; m < MM; m++) acc += es[m] * W_equ[m*EE + e];
    d_g_src[r*EE + e] = acc * SQRT_E;
}

// ---------------- h_src = h*16  (into h2[:,256:512]) --------------------------
__global__ void hsrc_kernel(const float* __restrict__ h)
{
    int i = blockIdx.x, e = threadIdx.x;
    d_h2[i*512 + 256 + e] = h[i*EE + e] * SQRT_E;
}

// ---------------- g2p + Gram ---------------------------------------------------
__global__ void gram_kernel(const float* __restrict__ W_gproj)
{
    __shared__ float gs[NV][EE];
    __shared__ float g2p[NV][32];
    int node = blockIdx.x;
    int t = threadIdx.x;
#pragma unroll
    for (int i = 0; i < NV; i++) gs[i][t] = d_g_src[(node*NV + i)*EE + t];
    __syncthreads();
    if (t < 96) {
        int i = t >> 5, a = t & 31;
        float acc = 0.f;
#pragma unroll 4
        for (int k2 = 0; k2 < EE; k2++) acc += gs[i][k2] * W_gproj[k2*32 + a];
        g2p[i][a] = acc;
    }
    __syncthreads();
#pragma unroll
    for (int o = t; o < 1024; o += 256) {
        int a = o >> 5, b = o & 31;
        float acc = g2p[0][a]*g2p[0][b] + g2p[1][a]*g2p[1][b] + g2p[2][a]*g2p[2][b];
        d_gram[node*1024 + o] = acc;
    }
}

// ---------------- fp16 tensor-core GEMM (ldmatrix + prefetch) -------------------
// C[row*ldc+col] = post( alpha*(A@B + bias) + resid[row*ldr+col] )
// A row-major [M,K], B row-major [K,Nn]. 64x64 tile, K-chunk 32, m16n8k16.
template<bool RELU, bool BIAS, bool RES, bool X2>
__global__ __launch_bounds__(256)
void gemm16(const float* __restrict__ A, const float* __restrict__ B,
            const float* __restrict__ bias, const float* __restrict__ resid,
            float* __restrict__ C, int K, int Nn,
            int ldr, int ldc, float alpha)
{
    __shared__ uint32_t Ahi[64][20];   // [m][k half2]
    __shared__ uint32_t Alo[64][20];
    __shared__ uint32_t Bhi[64][20];   // TRANSPOSED: [n][k half2]
    __shared__ uint32_t Blo[64][20];

    int tid = threadIdx.x, lane = tid & 31, w = tid >> 5;
    int m0 = blockIdx.y * 64, n0 = blockIdx.x * 64;
    int rs = 16 * (w >> 1);
    int cs = 32 * (w & 1);
    int g  = lane >> 3;

    int afr = tid >> 2;          // A fill: row 0..63
    int afq = tid & 3;           // A fill: k-group (8 floats)
    int bfn = tid & 63;          // B fill: col n 0..63
    int bfk = tid >> 6;          // B fill: k-group (8 floats)

    float acc[4][4] = {};
    float4 pa0, pa1;
    float pb[8];

    // prologue prefetch (k0 = 0)
    {
        const float4* ap = (const float4*)&A[(m0 + afr)*K + afq*8];
        pa0 = ap[0]; pa1 = ap[1];
#pragma unroll
        for (int i = 0; i < 8; i++) pb[i] = B[(bfk*8 + i)*Nn + n0 + bfn];
    }

    for (int k0 = 0; k0 < K; k0 += 32) {
        __syncthreads();
        // store prefetched tile (convert fp32 -> fp16 hi[/lo])
        if (X2) {
            uint32_t h0,l0,h1,l1;
            cvthl(pa0.x, pa0.y, h0, l0); cvthl(pa0.z, pa0.w, h1, l1);
            *(uint2*)&Ahi[afr][afq*4]   = make_uint2(h0,h1);
            *(uint2*)&Alo[afr][afq*4]   = make_uint2(l0,l1);
            cvthl(pa1.x, pa1.y, h0, l0); cvthl(pa1.z, pa1.w, h1, l1);
            *(uint2*)&Ahi[afr][afq*4+2] = make_uint2(h0,h1);
            *(uint2*)&Alo[afr][afq*4+2] = make_uint2(l0,l1);
            cvthl(pb[0], pb[1], h0, l0); cvthl(pb[2], pb[3], h1, l1);
            *(uint2*)&Bhi[bfn][bfk*4]   = make_uint2(h0,h1);
            *(uint2*)&Blo[bfn][bfk*4]   = make_uint2(l0,l1);
            cvthl(pb[4], pb[5], h0, l0); cvthl(pb[6], pb[7], h1, l1);
            *(uint2*)&Bhi[bfn][bfk*4+2] = make_uint2(h0,h1);
            *(uint2*)&Blo[bfn][bfk*4+2] = make_uint2(l0,l1);
        } else {
            *(uint2*)&Ahi[afr][afq*4]   = make_uint2(cvth(pa0.x,pa0.y), cvth(pa0.z,pa0.w));
            *(uint2*)&Ahi[afr][afq*4+2] = make_uint2(cvth(pa1.x,pa1.y), cvth(pa1.z,pa1.w));
            *(uint2*)&Bhi[bfn][bfk*4]   = make_uint2(cvth(pb[0],pb[1]), cvth(pb[2],pb[3]));
            *(uint2*)&Bhi[bfn][bfk*4+2] = make_uint2(cvth(pb[4],pb[5]), cvth(pb[6],pb[7]));
        }
        __syncthreads();
        // prefetch next chunk during compute
        if (k0 + 32 < K) {
            const float4* ap = (const float4*)&A[(m0 + afr)*K + k0 + 32 + afq*8];
            pa0 = ap[0]; pa1 = ap[1];
#pragma unroll
            for (int i = 0; i < 8; i++) pb[i] = B[(k0 + 32 + bfk*8 + i)*Nn + n0 + bfn];
        }
#pragma unroll
        for (int kk = 0; kk < 2; kk++) {
            uint32_t ah0,ah1,ah2,ah3;
            ldsm4(ah0,ah1,ah2,ah3, &Ahi[rs + (g&1)*8 + (lane&7)][kk*8 + (g>>1)*4]);
            uint32_t al0,al1,al2,al3;
            if (X2) ldsm4(al0,al1,al2,al3, &Alo[rs + (g&1)*8 + (lane&7)][kk*8 + (g>>1)*4]);
            uint32_t bh[8], bl[8];
#pragma unroll
            for (int jj = 0; jj < 2; jj++) {
                int brow = cs + jj*16 + (g>>1)*8 + (lane&7);
                int bcol = kk*8 + (g&1)*4;
                ldsm4(bh[jj*4+0],bh[jj*4+1],bh[jj*4+2],bh[jj*4+3], &Bhi[brow][bcol]);
                if (X2)
                    ldsm4(bl[jj*4+0],bl[jj*4+1],bl[jj*4+2],bl[jj*4+3], &Blo[brow][bcol]);
            }
#pragma unroll
            for (int j = 0; j < 4; j++) {
                uint32_t b0 = bh[(j>>1)*4 + (j&1)*2], b1 = bh[(j>>1)*4 + (j&1)*2 + 1];
                mma_f16(acc[j], ah0,ah1,ah2,ah3, b0, b1);
                if (X2) {
                    uint32_t c0 = bl[(j>>1)*4 + (j&1)*2], c1 = bl[(j>>1)*4 + (j&1)*2 + 1];
                    mma_f16(acc[j], al0,al1,al2,al3, b0, b1);
                    mma_f16(acc[j], ah0,ah1,ah2,ah3, c0, c1);
                }
            }
        }
    }

    // epilogue (C frag: c0,c1 at (r, 2q..2q+1); c2,c3 at r+8)
    int r0 = m0 + rs + (lane >> 2);
#pragma unroll
    for (int j = 0; j < 4; j++) {
        int col = n0 + cs + j*8 + 2*(lane & 3);
        float b0 = 0.f, b1 = 0.f;
        if (BIAS) { b0 = bias[col]; b1 = bias[col+1]; }
#pragma unroll
        for (int h2r = 0; h2r < 2; h2r++) {
            int row = r0 + h2r*8;
            float v0 = acc[j][2*h2r+0];
            float v1 = acc[j][2*h2r+1];
            if (BIAS) { v0 += b0; v1 += b1; }
            v0 *= alpha; v1 *= alpha;
            if (RES) {
                v0 += resid[row*ldr + col];
                v1 += resid[row*ldr + col + 1];
            }
            if (RELU) { v0 = fmaxf(v0, 0.f); v1 = fmaxf(v1, 0.f); }
            *(float2*)&C[row*ldc + col] = make_float2(v0, v1);
        }
    }
}

// ---------------- pack kernels -------------------------------------------------
__global__ void pack_k_kernel()
{
    int idx = blockIdx.x * 256 + threadIdx.x;     // over NN*128
    float a = d_kb[idx*2], b = d_kb[idx*2+1];
    cvthl(a, b, d_kh[idx], d_kl[idx]);
}

// combined V transposed: d_vt[h][c][node], c: 0..31 = v head-dim, 32..127 = vg
__global__ void pack_v_kernel()
{
    int idx = blockIdx.x * 256 + threadIdx.x;     // over HH*128*NN
    int node = idx & (NN-1);
    int hc = idx >> 12;
    int h = hc >> 7, c = hc & 127;
    float s;
    if (c < 32) s = d_vb[node*EE + h*DD + c];
    else {
        int iv = (c - 32) >> 5, dc = (c - 32) & 31;
        s = d_vgb[(node*NV + iv)*EE + h*DD + dc];
    }
    d_vt[idx] = __float2half_rn(s);
}

// ---------------- fp16 tensor-core flash attention (ldmatrix) ------------------
#define TQ 64
#define TK 64
// smem layout (bytes): KH 5120 | KL 5120 | VT 18432 | SS 17408 | PS 9216 | stats 768
#define ATTN_SMEM_BYTES (5120 + 5120 + 18432 + 17408 + 9216 + 768)

__global__ __launch_bounds__(256, 2)
void attn_f16_kernel(const float* __restrict__ q)
{
    extern __shared__ char smc[];
    uint32_t* KH = (uint32_t*)smc;                // [64][20] half2
    uint32_t* KL = KH + 64*20;                    // [64][20]
    uint32_t* VT = KL + 64*20;                    // [128][36] half2 (n-major, k contiguous)
    float*    SS = (float*)(VT + 128*36);         // [64][68] fp32 scores
    uint32_t* PS = (uint32_t*)(SS + 64*68);       // [64][36] half2 probs
    float*  rmax = (float*)(PS + 64*36);
    float*  rsum = rmax + 64;
    float*  ralf = rsum + 64;

    int tid  = threadIdx.x;
    int lane = tid & 31;
    int w    = tid >> 5;
    int g    = lane >> 3;
    int hh   = blockIdx.y;
    int hoff = hh * DD;
    int qbase = blockIdx.x * TQ;

    int rs = 16 * (w >> 1);      // warp row base
    int cs = 32 * (w & 1);       // warp S-col base
    int co = 64 * (w & 1);       // warp PV out-col base

    // ---- preload Q fragments fp16 hi/lo (2 k16 chunks) ----
    uint32_t qh[2][4], ql[2][4];
    {
        int gr0 = qbase + rs + (lane >> 2);
#pragma unroll
        for (int kk = 0; kk < 2; kk++) {
            int c0 = hoff + kk*16 + 2*(lane & 3);
            float2 x0 = *(const float2*)&q[gr0*EE + c0];
            float2 x1 = *(const float2*)&q[(gr0+8)*EE + c0];
            float2 x2 = *(const float2*)&q[gr0*EE + c0 + 8];
            float2 x3 = *(const float2*)&q[(gr0+8)*EE + c0 + 8];
            cvthl(x0.x, x0.y, qh[kk][0], ql[kk][0]);
            cvthl(x1.x, x1.y, qh[kk][1], ql[kk][1]);
            cvthl(x2.x, x2.y, qh[kk][2], ql[kk][2]);
            cvthl(x3.x, x3.y, qh[kk][3], ql[kk][3]);
        }
    }
    if (tid < TQ) { rmax[tid] = -1e30f; rsum[tid] = 0.f; }

    float o[8][4] = {};

    for (int kb = 0; kb < NN; kb += TK) {
        __syncthreads();
        // ---- fill K tile from packed global (hi/lo), vectorized ----
#pragma unroll
        for (int l = 0; l < 2; l++) {
            int idx = tid + l*256;
            int row = idx >> 3, cp = (idx & 7) * 2;
            int gg = (kb + row)*128 + hh*16 + cp;
            *(uint2*)&KH[row*20 + cp] = *(const uint2*)&d_kh[gg];
            *(uint2*)&KL[row*20 + cp] = *(const uint2*)&d_kl[gg];
        }
        // ---- fill V tile (transposed layout, contiguous in k) ----
#pragma unroll
        for (int l = 0; l < 4; l++) {
            int idx = tid + l*256;
            int row = idx >> 3;          // 0..127 (out col)
            int c16 = idx & 7;           // 8-half chunk
            uint4 vv = *(const uint4*)&d_vt[(hh*128 + row)*NN + kb + c16*8];
            *(uint4*)&VT[row*36 + c16*4] = vv;
        }
        __syncthreads();

        // ---- S = Q K^T (fp16 hi/lo), warp chunk 16x32, ldmatrix B-frags ----
        float sc[4][4];
#pragma unroll
        for (int j = 0; j < 4; j++)
#pragma unroll
            for (int i = 0; i < 4; i++) sc[j][i] = 0.f;
#pragma unroll
        for (int kk = 0; kk < 2; kk++) {
            uint32_t bh[8], bl[8];
#pragma unroll
            for (int jj = 0; jj < 2; jj++) {
                int nrow = cs + jj*16 + (g>>1)*8 + (lane&7);
                int kc   = kk*8 + (g&1)*4;
                ldsm4(bh[jj*4+0],bh[jj*4+1],bh[jj*4+2],bh[jj*4+3], &KH[nrow*20 + kc]);
                ldsm4(bl[jj*4+0],bl[jj*4+1],bl[jj*4+2],bl[jj*4+3], &KL[nrow*20 + kc]);
            }
#pragma unroll
            for (int j = 0; j < 4; j++) {
                uint32_t b0 = bh[(j>>1)*4 + (j&1)*2], b1 = bh[(j>>1)*4 + (j&1)*2 + 1];
                uint32_t c0 = bl[(j>>1)*4 + (j&1)*2], c1 = bl[(j>>1)*4 + (j&1)*2 + 1];
                mma_f16(sc[j], qh[kk][0], qh[kk][1], qh[kk][2], qh[kk][3], b0, b1);
                mma_f16(sc[j], ql[kk][0], ql[kk][1], ql[kk][2], ql[kk][3], b0, b1);
                mma_f16(sc[j], qh[kk][0], qh[kk][1], qh[kk][2], qh[kk][3], c0, c1);
            }
        }
#pragma unroll
        for (int j = 0; j < 4; j++) {
            int c0 = cs + j*8 + 2*(lane & 3);
            int r0 = rs + (lane >> 2);
            *(float2*)&SS[r0*68 + c0]     = make_float2(sc[j][0], sc[j][1]);
            *(float2*)&SS[(r0+8)*68 + c0] = make_float2(sc[j][2], sc[j][3]);
        }
        __syncthreads();

        // ---- online softmax: 4 threads per row, 16 cols each (vectorized) ----
        {
            int r = tid >> 2, qx = tid & 3;
            const float4* prow = (const float4*)&SS[r*68 + qx*16];
            float4 f[4];
#pragma unroll
            for (int i = 0; i < 4; i++) f[i] = prow[i];
            float m = -1e30f;
#pragma unroll
            for (int i = 0; i < 4; i++)
                m = fmaxf(m, fmaxf(fmaxf(f[i].x, f[i].y), fmaxf(f[i].z, f[i].w)));
            m = fmaxf(m, __shfl_xor_sync(0xffffffffu, m, 1));
            m = fmaxf(m, __shfl_xor_sync(0xffffffffu, m, 2));
            float mold = rmax[r];
            m = fmaxf(m, mold);
            float ps = 0.f;
#pragma unroll
            for (int i = 0; i < 4; i++) {
                float pa = fexp(f[i].x - m), pbv = fexp(f[i].y - m);
                float pc = fexp(f[i].z - m), pd  = fexp(f[i].w - m);
                __half ha = __float2half_rn(pa), hb = __float2half_rn(pbv);
                __half hc = __float2half_rn(pc), hd = __float2half_rn(pd);
                *(uint2*)&PS[r*36 + qx*8 + i*2] = make_uint2(packh2(ha, hb), packh2(hc, hd));
                ps += __half2float(ha) + __half2float(hb)
                    + __half2float(hc) + __half2float(hd);
            }
            ps += __shfl_xor_sync(0xffffffffu, ps, 1);
            ps += __shfl_xor_sync(0xffffffffu, ps, 2);
            if (qx == 0) {
                float alf = fexp(mold - m);
                rsum[r] = rsum[r]*alf + ps;
                rmax[r] = m;
                ralf[r] = alf;
            }
        }
        __syncthreads();

        // ---- rescale + P@V (single fp16), ldmatrix A- and B-frags ----
        {
            float a0s = ralf[rs + (lane >> 2)];
            float a1s = ralf[rs + 8 + (lane >> 2)];
#pragma unroll
            for (int j = 0; j < 8; j++) {
                o[j][0] *= a0s; o[j][1] *= a0s;
                o[j][2] *= a1s; o[j][3] *= a1s;
            }
        }
#pragma unroll
        for (int kk = 0; kk < 4; kk++) {
            uint32_t a0,a1,a2,a3;
            ldsm4(a0,a1,a2,a3, &PS[(rs + (g&1)*8 + (lane&7))*36 + kk*8 + (g>>1)*4]);
            uint32_t bv[16];
#pragma unroll
            for (int jj = 0; jj < 4; jj++) {
                int nrow = co + jj*16 + (g>>1)*8 + (lane&7);
                int kc   = kk*8 + (g&1)*4;
                ldsm4(bv[jj*4+0],bv[jj*4+1],bv[jj*4+2],bv[jj*4+3], &VT[nrow*36 + kc]);
            }
#pragma unroll
            for (int j = 0; j < 8; j++) {
                uint32_t b0 = bv[(j>>1)*4 + (j&1)*2], b1 = bv[(j>>1)*4 + (j&1)*2 + 1];
                mma_f16(o[j], a0, a1, a2, a3, b0, b1);
            }
        }
    }

    // ---- epilogue: normalize and scatter ----
    {
        int lr0 = rs + (lane >> 2);
        float inv0 = 1.0f / rsum[lr0];
        float inv1 = 1.0f / rsum[lr0 + 8];
        int gr0 = qbase + lr0;
        int gr1 = gr0 + 8;
#pragma unroll
        for (int j = 0; j < 8; j++) {
            int col = co + j*8 + 2*(lane & 3);
#pragma unroll
            for (int s = 0; s < 2; s++) {
                int c = col + s;
                float v0 = o[j][s]   * inv0;
                float v1 = o[j][2+s] * inv1;
                if (c < 32) {
                    d_outv[gr0*EE + hoff + c] = v0;
                    d_outv[gr1*EE + hoff + c] = v1;
                } else {
                    int iv = (c - 32) >> 5, dc = (c - 32) & 31;
                    d_outg[(gr0*NV + iv)*EE + hoff + dc] = v0;
                    d_outg[(gr1*NV + iv)*EE + hoff + dc] = v1;
                }
            }
        }
    }
}

// ---------------- equ_out = gnew @ W_gdec  ([*,256]@[256,16]) ------------------
__global__ void gdec_kernel(const float* __restrict__ W_gdec, float* __restrict__ out)
{
    __shared__ float gs[16][EE];
    int rbase = blockIdx.x * 16;
    int t = threadIdx.x;
    for (int idx = t; idx < 16*EE; idx += 256)
        gs[idx >> 8][idx & 255] = d_gnew[(rbase + (idx >> 8))*EE + (idx & 255)];
    __syncthreads();
    int lr = t >> 4, c = t & 15;
    float acc = 0.f;
#pragma unroll 4
    for (int k2 = 0; k2 < EE; k2++) acc += gs[lr][k2] * W_gdec[k2*MM + c];
    out[(rbase + lr)*MM + c] = acc;
}

// ------------------------------------------------------------------------------
extern "C" void kernel_launch(void* const* d_in, const int* in_sizes, int n_in,
                              void* d_out, int out_size)
{
    const float* equ    = (const float*)d_in[0];
    const float* h      = (const float*)d_in[1];
    const float* W_equ  = (const float*)d_in[4];
    const float* W_gproj= (const float*)d_in[5];
    const float* W_vg   = (const float*)d_in[6];
    const float* W_g1   = (const float*)d_in[7];
    const float* b_g1   = (const float*)d_in[8];
    const float* W_g2   = (const float*)d_in[9];
    const float* b_g2   = (const float*)d_in[10];
    const float* W_q    = (const float*)d_in[11];
    const float* b_q    = (const float*)d_in[12];
    const float* W_k    = (const float*)d_in[13];
    const float* b_k    = (const float*)d_in[14];
    const float* W_v    = (const float*)d_in[15];
    const float* b_v    = (const float*)d_in[16];
    const float* W_ng   = (const float*)d_in[17];
    const float* b_ng   = (const float*)d_in[18];
    const float* W_gout = (const float*)d_in[19];
    const float* W_gdec = (const float*)d_in[20];
    const float* W_hdec = (const float*)d_in[21];
    const float* b_hdec = (const float*)d_in[22];
    float* out = (float*)d_out;

    float *g_src, *h2, *gram, *t1, *qb, *kb, *vb, *vgb, *outv, *outg, *hnew, *gnew;
    cudaGetSymbolAddress((void**)&g_src, d_g_src);
    cudaGetSymbolAddress((void**)&h2,    d_h2);
    cudaGetSymbolAddress((void**)&gram,  d_gram);
    cudaGetSymbolAddress((void**)&t1,    d_t1);
    cudaGetSymbolAddress((void**)&qb,    d_qb);
    cudaGetSymbolAddress((void**)&kb,    d_kb);
    cudaGetSymbolAddress((void**)&vb,    d_vb);
    cudaGetSymbolAddress((void**)&vgb,   d_vgb);
    cudaGetSymbolAddress((void**)&outv,  d_outv);
    cudaGetSymbolAddress((void**)&outg,  d_outg);
    cudaGetSymbolAddress((void**)&hnew,  d_hnew);
    cudaGetSymbolAddress((void**)&gnew,  d_gnew);

    // 1) prep
    gsrc_kernel<<<NR, 256>>>(equ, W_equ);
    hsrc_kernel<<<NN, 256>>>(h);
    gram_kernel<<<NN, 256>>>(W_gproj);

    // 2) MLP on gram (logit-critical -> X2)
    gemm16<true, true, false, true><<<dim3(512/64, NN/64), 256>>>(
        gram, W_g1, b_g1, nullptr, t1, 1024, 512, 0, 512, 1.f);
    gemm16<false, true, false, true><<<dim3(256/64, NN/64), 256>>>(
        t1, W_g2, b_g2, nullptr, h2, 512, 256, 0, 512, 1.f);

    // 3) q,k (X2), v,vg (single)
    gemm16<false, true, false, true><<<dim3(256/64, NN/64), 256>>>(
        h2, W_q, b_q, nullptr, qb, 512, 256, 0, 256, SCALING);
    gemm16<false, true, false, true><<<dim3(256/64, NN/64), 256>>>(
        h2, W_k, b_k, nullptr, kb, 512, 256, 0, 256, 1.f);
    gemm16<false, true, false, false><<<dim3(256/64, NN/64), 256>>>(
        h2, W_v, b_v, nullptr, vb, 512, 256, 0, 256, 1.f);
    gemm16<false, false, false, false><<<dim3(256/64, NR/64), 256>>>(
        g_src, W_vg, nullptr, nullptr, vgb, 256, 256, 0, 256, 1.f);

    // 3b) pack K (hi/lo fp16) and combined V (fp16, transposed)
    pack_k_kernel<<<NN*128/256, 256>>>();
    pack_v_kernel<<<HH*128*NN/256, 256>>>();

    // 4) fp16 tensor-core flash attention
    cudaFuncSetAttribute(attn_f16_kernel, cudaFuncAttributeMaxDynamicSharedMemorySize,
                         ATTN_SMEM_BYTES);
    attn_f16_kernel<<<dim3(NN/TQ, HH), 256, ATTN_SMEM_BYTES>>>(qb);

    // 5) h path (single)
    gemm16<false, true, true, false><<<dim3(256/64, NN/64), 256>>>(
        outv, W_ng, b_ng, h2 + 256, hnew, 256, 256, 512, 256, 1.f);
    gemm16<false, true, false, false><<<dim3(256/64, NN/64), 256>>>(
        hnew, W_hdec, b_hdec, nullptr, out + NR*MM, 256, 256, 0, 256, 1.f);

    // 6) g path (single)
    gemm16<false, false, true, false><<<dim3(256/64, NR/64), 256>>>(
        outg, W_gout, nullptr, g_src, gnew, 256, 256, 256, 256, 1.f);
    gdec_kernel<<<NR/16, 256>>>(W_gdec, out);
}

// round 10
// speedup vs baseline: 3.5601x; 1.1320x over previous
#include <cuda_runtime.h>
#include <cuda_fp16.h>
#include <math.h>
#include <stdint.h>

// Shapes (fixed for this problem)
#define NN   4096
#define NV   3
#define MM   16
#define EE   256
#define HH   8
#define DD   32
#define NR   (NN*NV)
#define SQRT_E 16.0f
#define SCALING 0.17677669529663687f   // 32^-0.5

// ---------------- scratch (device globals; no allocation allowed) -------------
__device__ float d_g_src[NR*EE];
__device__ float d_h2[NN*2*EE];        // [N, 512] = [g2 | h_src]
__device__ float d_gram[NN*1024];
__device__ float d_t1[NN*512];
__device__ float d_qb[NN*EE];
__device__ float d_kb[NN*EE];
__device__ float d_vb[NN*EE];
__device__ float d_vgb[NR*EE];
__device__ float d_outv[NN*EE];
__device__ float d_outg[NR*EE];
__device__ float d_hnew[NN*EE];
__device__ float d_gnew[NR*EE];
// fp16-packed attention operands
__device__ uint32_t d_kh[NN*128];      // K hi, half2 words: [node][128]
__device__ uint32_t d_kl[NN*128];      // K lo
__device__ __half  d_vt[HH*128*NN];    // combined V transposed: [h][c=128][node]

// ---------------- helpers ------------------------------------------------------
__device__ __forceinline__ uint32_t packh2(__half a, __half b) {
    __half2 t = __halves2half2(a, b);
    return *reinterpret_cast<uint32_t*>(&t);
}
__device__ __forceinline__ uint32_t cvth(float a, float b) {
    __half2 t = __floats2half2_rn(a, b);
    return *reinterpret_cast<uint32_t*>(&t);
}
__device__ __forceinline__ void cvthl(float a, float b, uint32_t& hi, uint32_t& lo) {
    __half ha = __float2half_rn(a), hb = __float2half_rn(b);
    __half la = __float2half_rn(a - __half2float(ha));
    __half lb = __float2half_rn(b - __half2float(hb));
    hi = packh2(ha, hb);
    lo = packh2(la, lb);
}

__device__ __forceinline__ void mma_f16(float c[4],
    uint32_t a0, uint32_t a1, uint32_t a2, uint32_t a3,
    uint32_t b0, uint32_t b1)
{
    asm volatile(
        "mma.sync.aligned.m16n8k16.row.col.f32.f16.f16.f32 "
        "{%0,%1,%2,%3}, {%4,%5,%6,%7}, {%8,%9}, {%0,%1,%2,%3};\n"
        : "+f"(c[0]), "+f"(c[1]), "+f"(c[2]), "+f"(c[3])
        : "r"(a0), "r"(a1), "r"(a2), "r"(a3), "r"(b0), "r"(b1));
}

__device__ __forceinline__ void ldsm4(uint32_t& r0, uint32_t& r1,
                                      uint32_t& r2, uint32_t& r3, const void* p)
{
    uint32_t addr = (uint32_t)__cvta_generic_to_shared(p);
    asm volatile("ldmatrix.sync.aligned.m8n8.x4.shared.b16 {%0,%1,%2,%3}, [%4];"
                 : "=r"(r0), "=r"(r1), "=r"(r2), "=r"(r3) : "r"(addr));
}

// fast e^x via FMA-only path (no MUFU).
__device__ __forceinline__ float fexp(float x) {
    float y = x * 1.4426950408889634f;
    y = fmaxf(y, -126.0f);
    float n = rintf(y);
    float f = y - n;
    float p = 1.3333558146e-3f;
    p = fmaf(p, f, 9.6181291076e-3f);
    p = fmaf(p, f, 5.5504108665e-2f);
    p = fmaf(p, f, 2.4022650696e-1f);
    p = fmaf(p, f, 6.9314718056e-1f);
    p = fmaf(p, f, 1.0f);
    int e = (int)n;
    return p * __int_as_float((e + 127) << 23);
}

// ---------------- g_src = (equ @ W_equ) * 16 ----------------------------------
__global__ void gsrc_kernel(const float* __restrict__ equ,
                            const float* __restrict__ W_equ)
{
    __shared__ float es[MM];
    int r = blockIdx.x;
    int e = threadIdx.x;
    if (e < MM) es[e] = equ[r*MM + e];
    __syncthreads();
    float acc = 0.f;
#pragma unroll
    for (int m = 0; m < MM; m++) acc += es[m] * W_equ[m*EE + e];
    d_g_src[r*EE + e] = acc * SQRT_E;
}

// ---------------- h_src = h*16  (into h2[:,256:512]) --------------------------
__global__ void hsrc_kernel(const float* __restrict__ h)
{
    int i = blockIdx.x, e = threadIdx.x;
    d_h2[i*512 + 256 + e] = h[i*EE + e] * SQRT_E;
}

// ---------------- g2p + Gram ---------------------------------------------------
__global__ void gram_kernel(const float* __restrict__ W_gproj)
{
    __shared__ float gs[NV][EE];
    __shared__ float g2p[NV][32];
    int node = blockIdx.x;
    int t = threadIdx.x;
#pragma unroll
    for (int i = 0; i < NV; i++) gs[i][t] = d_g_src[(node*NV + i)*EE + t];
    __syncthreads();
    if (t < 96) {
        int i = t >> 5, a = t & 31;
        float acc = 0.f;
#pragma unroll 4
        for (int k2 = 0; k2 < EE; k2++) acc += gs[i][k2] * W_gproj[k2*32 + a];
        g2p[i][a] = acc;
    }
    __syncthreads();
#pragma unroll
    for (int o = t; o < 1024; o += 256) {
        int a = o >> 5, b = o & 31;
        float acc = g2p[0][a]*g2p[0][b] + g2p[1][a]*g2p[1][b] + g2p[2][a]*g2p[2][b];
        d_gram[node*1024 + o] = acc;
    }
}

// ---------------- fp16 tensor-core GEMM (ldmatrix + prefetch) -------------------
template<bool RELU, bool BIAS, bool RES, bool X2>
__global__ __launch_bounds__(256)
void gemm16(const float* __restrict__ A, const float* __restrict__ B,
            const float* __restrict__ bias, const float* __restrict__ resid,
            float* __restrict__ C, int K, int Nn,
            int ldr, int ldc, float alpha)
{
    __shared__ uint32_t Ahi[64][20];   // [m][k half2]
    __shared__ uint32_t Alo[64][20];
    __shared__ uint32_t Bhi[64][20];   // TRANSPOSED: [n][k half2]
    __shared__ uint32_t Blo[64][20];

    int tid = threadIdx.x, lane = tid & 31, w = tid >> 5;
    int m0 = blockIdx.y * 64, n0 = blockIdx.x * 64;
    int rs = 16 * (w >> 1);
    int cs = 32 * (w & 1);
    int g  = lane >> 3;

    int afr = tid >> 2;          // A fill: row 0..63
    int afq = tid & 3;           // A fill: k-group (8 floats)
    int bfn = tid & 63;          // B fill: col n 0..63
    int bfk = tid >> 6;          // B fill: k-group (8 floats)

    float acc[4][4] = {};
    float4 pa0, pa1;
    float pb[8];

    // prologue prefetch (k0 = 0)
    {
        const float4* ap = (const float4*)&A[(m0 + afr)*K + afq*8];
        pa0 = ap[0]; pa1 = ap[1];
#pragma unroll
        for (int i = 0; i < 8; i++) pb[i] = B[(bfk*8 + i)*Nn + n0 + bfn];
    }

    for (int k0 = 0; k0 < K; k0 += 32) {
        __syncthreads();
        // store prefetched tile (convert fp32 -> fp16 hi[/lo])
        if (X2) {
            uint32_t h0,l0,h1,l1;
            cvthl(pa0.x, pa0.y, h0, l0); cvthl(pa0.z, pa0.w, h1, l1);
            *(uint2*)&Ahi[afr][afq*4]   = make_uint2(h0,h1);
            *(uint2*)&Alo[afr][afq*4]   = make_uint2(l0,l1);
            cvthl(pa1.x, pa1.y, h0, l0); cvthl(pa1.z, pa1.w, h1, l1);
            *(uint2*)&Ahi[afr][afq*4+2] = make_uint2(h0,h1);
            *(uint2*)&Alo[afr][afq*4+2] = make_uint2(l0,l1);
            cvthl(pb[0], pb[1], h0, l0); cvthl(pb[2], pb[3], h1, l1);
            *(uint2*)&Bhi[bfn][bfk*4]   = make_uint2(h0,h1);
            *(uint2*)&Blo[bfn][bfk*4]   = make_uint2(l0,l1);
            cvthl(pb[4], pb[5], h0, l0); cvthl(pb[6], pb[7], h1, l1);
            *(uint2*)&Bhi[bfn][bfk*4+2] = make_uint2(h0,h1);
            *(uint2*)&Blo[bfn][bfk*4+2] = make_uint2(l0,l1);
        } else {
            *(uint2*)&Ahi[afr][afq*4]   = make_uint2(cvth(pa0.x,pa0.y), cvth(pa0.z,pa0.w));
            *(uint2*)&Ahi[afr][afq*4+2] = make_uint2(cvth(pa1.x,pa1.y), cvth(pa1.z,pa1.w));
            *(uint2*)&Bhi[bfn][bfk*4]   = make_uint2(cvth(pb[0],pb[1]), cvth(pb[2],pb[3]));
            *(uint2*)&Bhi[bfn][bfk*4+2] = make_uint2(cvth(pb[4],pb[5]), cvth(pb[6],pb[7]));
        }
        __syncthreads();
        // prefetch next chunk during compute
        if (k0 + 32 < K) {
            const float4* ap = (const float4*)&A[(m0 + afr)*K + k0 + 32 + afq*8];
            pa0 = ap[0]; pa1 = ap[1];
#pragma unroll
            for (int i = 0; i < 8; i++) pb[i] = B[(k0 + 32 + bfk*8 + i)*Nn + n0 + bfn];
        }
#pragma unroll
        for (int kk = 0; kk < 2; kk++) {
            uint32_t ah0,ah1,ah2,ah3;
            ldsm4(ah0,ah1,ah2,ah3, &Ahi[rs + (g&1)*8 + (lane&7)][kk*8 + (g>>1)*4]);
            uint32_t al0,al1,al2,al3;
            if (X2) ldsm4(al0,al1,al2,al3, &Alo[rs + (g&1)*8 + (lane&7)][kk*8 + (g>>1)*4]);
            uint32_t bh[8], bl[8];
#pragma unroll
            for (int jj = 0; jj < 2; jj++) {
                int brow = cs + jj*16 + (g>>1)*8 + (lane&7);
                int bcol = kk*8 + (g&1)*4;
                ldsm4(bh[jj*4+0],bh[jj*4+1],bh[jj*4+2],bh[jj*4+3], &Bhi[brow][bcol]);
                if (X2)
                    ldsm4(bl[jj*4+0],bl[jj*4+1],bl[jj*4+2],bl[jj*4+3], &Blo[brow][bcol]);
            }
#pragma unroll
            for (int j = 0; j < 4; j++) {
                uint32_t b0 = bh[(j>>1)*4 + (j&1)*2], b1 = bh[(j>>1)*4 + (j&1)*2 + 1];
                mma_f16(acc[j], ah0,ah1,ah2,ah3, b0, b1);
                if (X2) {
                    uint32_t c0 = bl[(j>>1)*4 + (j&1)*2], c1 = bl[(j>>1)*4 + (j&1)*2 + 1];
                    mma_f16(acc[j], al0,al1,al2,al3, b0, b1);
                    mma_f16(acc[j], ah0,ah1,ah2,ah3, c0, c1);
                }
            }
        }
    }

    // epilogue
    int r0 = m0 + rs + (lane >> 2);
#pragma unroll
    for (int j = 0; j < 4; j++) {
        int col = n0 + cs + j*8 + 2*(lane & 3);
        float b0 = 0.f, b1 = 0.f;
        if (BIAS) { b0 = bias[col]; b1 = bias[col+1]; }
#pragma unroll
        for (int h2r = 0; h2r < 2; h2r++) {
            int row = r0 + h2r*8;
            float v0 = acc[j][2*h2r+0];
            float v1 = acc[j][2*h2r+1];
            if (BIAS) { v0 += b0; v1 += b1; }
            v0 *= alpha; v1 *= alpha;
            if (RES) {
                v0 += resid[row*ldr + col];
                v1 += resid[row*ldr + col + 1];
            }
            if (RELU) { v0 = fmaxf(v0, 0.f); v1 = fmaxf(v1, 0.f); }
            *(float2*)&C[row*ldc + col] = make_float2(v0, v1);
        }
    }
}

// ---------------- pack kernels -------------------------------------------------
__global__ void pack_k_kernel()
{
    int idx = blockIdx.x * 256 + threadIdx.x;     // over NN*128
    float a = d_kb[idx*2], b = d_kb[idx*2+1];
    cvthl(a, b, d_kh[idx], d_kl[idx]);
}

// combined V transposed: d_vt[h][c][node], c: 0..31 = v head-dim, 32..127 = vg
__global__ void pack_v_kernel()
{
    int idx = blockIdx.x * 256 + threadIdx.x;     // over HH*128*NN
    int node = idx & (NN-1);
    int hc = idx >> 12;
    int h = hc >> 7, c = hc & 127;
    float s;
    if (c < 32) s = d_vb[node*EE + h*DD + c];
    else {
        int iv = (c - 32) >> 5, dc = (c - 32) & 31;
        s = d_vgb[(node*NV + iv)*EE + h*DD + dc];
    }
    d_vt[idx] = __float2half_rn(s);
}

// ---------------- register-resident fp16 flash attention (FA2-style) -----------
// 4 warps / CTA, TQ=64: each warp owns 16 query rows x full 64-wide S in regs.
// Softmax + P entirely in registers; smem only for K (hi/lo) and combined V.
#define ATQ 64
#define ATK 64
// smem: KH[64][20] + KL[64][20] + VT[128][36]  (uint32 words)
#define AT2_SMEM_BYTES ((64*20*2 + 128*36)*4)

__global__ __launch_bounds__(128, 3)
void attn_reg_kernel(const float* __restrict__ q)
{
    extern __shared__ char smc[];
    uint32_t* KH = (uint32_t*)smc;                // [64][20] half2
    uint32_t* KL = KH + 64*20;
    uint32_t* VT = KL + 64*20;                    // [128][36] half2 (n-major, k contig)

    int tid  = threadIdx.x;
    int lane = tid & 31;
    int w    = tid >> 5;         // 0..3
    int g    = lane >> 3;
    int hh   = blockIdx.y;
    int hoff = hh * DD;
    int qbase = blockIdx.x * ATQ;
    int wbase = w * 16;          // warp's 16 query rows

    // ---- preload Q fragments fp16 hi/lo (2 k16 chunks) ----
    uint32_t qh[2][4], ql[2][4];
    {
        int gr0 = qbase + wbase + (lane >> 2);
#pragma unroll
        for (int kk = 0; kk < 2; kk++) {
            int c0 = hoff + kk*16 + 2*(lane & 3);
            float2 x0 = *(const float2*)&q[gr0*EE + c0];
            float2 x1 = *(const float2*)&q[(gr0+8)*EE + c0];
            float2 x2 = *(const float2*)&q[gr0*EE + c0 + 8];
            float2 x3 = *(const float2*)&q[(gr0+8)*EE + c0 + 8];
            cvthl(x0.x, x0.y, qh[kk][0], ql[kk][0]);
            cvthl(x1.x, x1.y, qh[kk][1], ql[kk][1]);
            cvthl(x2.x, x2.y, qh[kk][2], ql[kk][2]);
            cvthl(x3.x, x3.y, qh[kk][3], ql[kk][3]);
        }
    }

    float rmax0 = -1e30f, rmax1 = -1e30f;
    float rsum0 = 0.f, rsum1 = 0.f;
    float acc[16][4] = {};       // 16 n8-frags covering 128 out cols

    for (int kb = 0; kb < NN; kb += ATK) {
        __syncthreads();
        // ---- fill K tile from packed global (hi/lo), 128 threads ----
#pragma unroll
        for (int l = 0; l < 4; l++) {
            int idx = tid + l*128;
            int row = idx >> 3, cp = (idx & 7) * 2;
            int gg = (kb + row)*128 + hh*16 + cp;
            *(uint2*)&KH[row*20 + cp] = *(const uint2*)&d_kh[gg];
            *(uint2*)&KL[row*20 + cp] = *(const uint2*)&d_kl[gg];
        }
        // ---- fill combined V tile (transposed, contiguous in k) ----
#pragma unroll
        for (int l = 0; l < 8; l++) {
            int idx = tid + l*128;
            int row = idx >> 3;          // 0..127 (out col)
            int c16 = idx & 7;           // 8-half chunk
            uint4 vv = *(const uint4*)&d_vt[(hh*128 + row)*NN + kb + c16*8];
            *(uint4*)&VT[row*36 + c16*4] = vv;
        }
        __syncthreads();

        // ---- S = Q K^T (fp16 hi/lo): warp computes 16 rows x 64 cols ----
        float sc[8][4];
#pragma unroll
        for (int j = 0; j < 8; j++)
#pragma unroll
            for (int i = 0; i < 4; i++) sc[j][i] = 0.f;
#pragma unroll
        for (int kk = 0; kk < 2; kk++) {
#pragma unroll
            for (int jj = 0; jj < 4; jj++) {
                int nrow = jj*16 + (g>>1)*8 + (lane&7);
                int kc   = kk*8 + (g&1)*4;
                uint32_t bh[4], bl[4];
                ldsm4(bh[0],bh[1],bh[2],bh[3], &KH[nrow*20 + kc]);
                ldsm4(bl[0],bl[1],bl[2],bl[3], &KL[nrow*20 + kc]);
#pragma unroll
                for (int jw = 0; jw < 2; jw++) {
                    int j = 2*jj + jw;
                    uint32_t b0 = bh[jw*2], b1 = bh[jw*2+1];
                    uint32_t c0 = bl[jw*2], c1 = bl[jw*2+1];
                    mma_f16(sc[j], qh[kk][0], qh[kk][1], qh[kk][2], qh[kk][3], b0, b1);
                    mma_f16(sc[j], ql[kk][0], ql[kk][1], ql[kk][2], ql[kk][3], b0, b1);
                    mma_f16(sc[j], qh[kk][0], qh[kk][1], qh[kk][2], qh[kk][3], c0, c1);
                }
            }
        }

        // ---- online softmax fully in registers (quad shfl over 4 lanes) ----
        float m0 = rmax0, m1 = rmax1;
#pragma unroll
        for (int j = 0; j < 8; j++) {
            m0 = fmaxf(m0, fmaxf(sc[j][0], sc[j][1]));
            m1 = fmaxf(m1, fmaxf(sc[j][2], sc[j][3]));
        }
        m0 = fmaxf(m0, __shfl_xor_sync(0xffffffffu, m0, 1));
        m0 = fmaxf(m0, __shfl_xor_sync(0xffffffffu, m0, 2));
        m1 = fmaxf(m1, __shfl_xor_sync(0xffffffffu, m1, 1));
        m1 = fmaxf(m1, __shfl_xor_sync(0xffffffffu, m1, 2));
        float alf0 = fexp(rmax0 - m0);
        float alf1 = fexp(rmax1 - m1);
        rmax0 = m0; rmax1 = m1;

        uint32_t pp0[8], pp1[8];
        float ps0 = 0.f, ps1 = 0.f;
#pragma unroll
        for (int j = 0; j < 8; j++) {
            __half ha = __float2half_rn(fexp(sc[j][0] - m0));
            __half hb = __float2half_rn(fexp(sc[j][1] - m0));
            __half hc = __float2half_rn(fexp(sc[j][2] - m1));
            __half hd = __float2half_rn(fexp(sc[j][3] - m1));
            pp0[j] = packh2(ha, hb);
            pp1[j] = packh2(hc, hd);
            ps0 += __half2float(ha) + __half2float(hb);
            ps1 += __half2float(hc) + __half2float(hd);
        }
        ps0 += __shfl_xor_sync(0xffffffffu, ps0, 1);
        ps0 += __shfl_xor_sync(0xffffffffu, ps0, 2);
        ps1 += __shfl_xor_sync(0xffffffffu, ps1, 1);
        ps1 += __shfl_xor_sync(0xffffffffu, ps1, 2);
        rsum0 = rsum0*alf0 + ps0;
        rsum1 = rsum1*alf1 + ps1;

        // ---- rescale accumulators ----
#pragma unroll
        for (int j = 0; j < 16; j++) {
            acc[j][0] *= alf0; acc[j][1] *= alf0;
            acc[j][2] *= alf1; acc[j][3] *= alf1;
        }

        // ---- P@V (single fp16), P register-resident as A-frags ----
#pragma unroll
        for (int kk = 0; kk < 4; kk++) {
            uint32_t a0 = pp0[2*kk],   a1 = pp1[2*kk];
            uint32_t a2 = pp0[2*kk+1], a3 = pp1[2*kk+1];
#pragma unroll
            for (int jj = 0; jj < 8; jj++) {
                int nrow = jj*16 + (g>>1)*8 + (lane&7);
                int kc   = kk*8 + (g&1)*4;
                uint32_t b[4];
                ldsm4(b[0], b[1], b[2], b[3], &VT[nrow*36 + kc]);
                mma_f16(acc[2*jj],   a0, a1, a2, a3, b[0], b[1]);
                mma_f16(acc[2*jj+1], a0, a1, a2, a3, b[2], b[3]);
            }
        }
    }

    // ---- epilogue: normalize and scatter ----
    {
        float inv0 = 1.0f / rsum0;
        float inv1 = 1.0f / rsum1;
        int gr0 = qbase + wbase + (lane >> 2);
        int gr1 = gr0 + 8;
#pragma unroll
        for (int j = 0; j < 16; j++) {
            int col = j*8 + 2*(lane & 3);
            float2 v0 = make_float2(acc[j][0]*inv0, acc[j][1]*inv0);
            float2 v1 = make_float2(acc[j][2]*inv1, acc[j][3]*inv1);
            if (col < 32) {
                *(float2*)&d_outv[gr0*EE + hoff + col] = v0;
                *(float2*)&d_outv[gr1*EE + hoff + col] = v1;
            } else {
                int iv = (col - 32) >> 5, dc = (col - 32) & 31;
                *(float2*)&d_outg[(gr0*NV + iv)*EE + hoff + dc] = v0;
                *(float2*)&d_outg[(gr1*NV + iv)*EE + hoff + dc] = v1;
            }
        }
    }
}

// ---------------- equ_out = gnew @ W_gdec  ([*,256]@[256,16]) ------------------
__global__ void gdec_kernel(const float* __restrict__ W_gdec, float* __restrict__ out)
{
    __shared__ float gs[16][EE];
    int rbase = blockIdx.x * 16;
    int t = threadIdx.x;
    for (int idx = t; idx < 16*EE; idx += 256)
        gs[idx >> 8][idx & 255] = d_gnew[(rbase + (idx >> 8))*EE + (idx & 255)];
    __syncthreads();
    int lr = t >> 4, c = t & 15;
    float acc = 0.f;
#pragma unroll 4
    for (int k2 = 0; k2 < EE; k2++) acc += gs[lr][k2] * W_gdec[k2*MM + c];
    out[(rbase + lr)*MM + c] = acc;
}

// ------------------------------------------------------------------------------
extern "C" void kernel_launch(void* const* d_in, const int* in_sizes, int n_in,
                              void* d_out, int out_size)
{
    const float* equ    = (const float*)d_in[0];
    const float* h      = (const float*)d_in[1];
    const float* W_equ  = (const float*)d_in[4];
    const float* W_gproj= (const float*)d_in[5];
    const float* W_vg   = (const float*)d_in[6];
    const float* W_g1   = (const float*)d_in[7];
    const float* b_g1   = (const float*)d_in[8];
    const float* W_g2   = (const float*)d_in[9];
    const float* b_g2   = (const float*)d_in[10];
    const float* W_q    = (const float*)d_in[11];
    const float* b_q    = (const float*)d_in[12];
    const float* W_k    = (const float*)d_in[13];
    const float* b_k    = (const float*)d_in[14];
    const float* W_v    = (const float*)d_in[15];
    const float* b_v    = (const float*)d_in[16];
    const float* W_ng   = (const float*)d_in[17];
    const float* b_ng   = (const float*)d_in[18];
    const float* W_gout = (const float*)d_in[19];
    const float* W_gdec = (const float*)d_in[20];
    const float* W_hdec = (const float*)d_in[21];
    const float* b_hdec = (const float*)d_in[22];
    float* out = (float*)d_out;

    float *g_src, *h2, *gram, *t1, *qb, *kb, *vb, *vgb, *outv, *outg, *hnew, *gnew;
    cudaGetSymbolAddress((void**)&g_src, d_g_src);
    cudaGetSymbolAddress((void**)&h2,    d_h2);
    cudaGetSymbolAddress((void**)&gram,  d_gram);
    cudaGetSymbolAddress((void**)&t1,    d_t1);
    cudaGetSymbolAddress((void**)&qb,    d_qb);
    cudaGetSymbolAddress((void**)&kb,    d_kb);
    cudaGetSymbolAddress((void**)&vb,    d_vb);
    cudaGetSymbolAddress((void**)&vgb,   d_vgb);
    cudaGetSymbolAddress((void**)&outv,  d_outv);
    cudaGetSymbolAddress((void**)&outg,  d_outg);
    cudaGetSymbolAddress((void**)&hnew,  d_hnew);
    cudaGetSymbolAddress((void**)&gnew,  d_gnew);

    // 1) prep
    gsrc_kernel<<<NR, 256>>>(equ, W_equ);
    hsrc_kernel<<<NN, 256>>>(h);
    gram_kernel<<<NN, 256>>>(W_gproj);

    // 2) MLP on gram (logit-critical -> X2)
    gemm16<true, true, false, true><<<dim3(512/64, NN/64), 256>>>(
        gram, W_g1, b_g1, nullptr, t1, 1024, 512, 0, 512, 1.f);
    gemm16<false, true, false, true><<<dim3(256/64, NN/64), 256>>>(
        t1, W_g2, b_g2, nullptr, h2, 512, 256, 0, 512, 1.f);

    // 3) q,k (X2), v,vg (single)
    gemm16<false, true, false, true><<<dim3(256/64, NN/64), 256>>>(
        h2, W_q, b_q, nullptr, qb, 512, 256, 0, 256, SCALING);
    gemm16<false, true, false, true><<<dim3(256/64, NN/64), 256>>>(
        h2, W_k, b_k, nullptr, kb, 512, 256, 0, 256, 1.f);
    gemm16<false, true, false, false><<<dim3(256/64, NN/64), 256>>>(
        h2, W_v, b_v, nullptr, vb, 512, 256, 0, 256, 1.f);
    gemm16<false, false, false, false><<<dim3(256/64, NR/64), 256>>>(
        g_src, W_vg, nullptr, nullptr, vgb, 256, 256, 0, 256, 1.f);

    // 3b) pack K (hi/lo fp16) and combined V (fp16, transposed)
    pack_k_kernel<<<NN*128/256, 256>>>();
    pack_v_kernel<<<HH*128*NN/256, 256>>>();

    // 4) register-resident fp16 flash attention
    cudaFuncSetAttribute(attn_reg_kernel, cudaFuncAttributeMaxDynamicSharedMemorySize,
                         AT2_SMEM_BYTES);
    attn_reg_kernel<<<dim3(NN/ATQ, HH), 128, AT2_SMEM_BYTES>>>(qb);

    // 5) h path (single)
    gemm16<false, true, true, false><<<dim3(256/64, NN/64), 256>>>(
        outv, W_ng, b_ng, h2 + 256, hnew, 256, 256, 512, 256, 1.f);
    gemm16<false, true, false, false><<<dim3(256/64, NN/64), 256>>>(
        hnew, W_hdec, b_hdec, nullptr, out + NR*MM, 256, 256, 0, 256, 1.f);

    // 6) g path (single)
    gemm16<false, false, true, false><<<dim3(256/64, NR/64), 256>>>(
        outg, W_gout, nullptr, g_src, gnew, 256, 256, 256, 256, 1.f);
    gdec_kernel<<<NR/16, 256>>>(W_gdec, out);
}

// round 11
// speedup vs baseline: 3.8905x; 1.0928x over previous
#include <cuda_runtime.h>
#include <cuda_fp16.h>
#include <math.h>
#include <stdint.h>

// Shapes (fixed for this problem)
#define NN   4096
#define NV   3
#define MM   16
#define EE   256
#define HH   8
#define DD   32
#define NR   (NN*NV)
#define SQRT_E 16.0f
#define SCALING 0.17677669529663687f   // 32^-0.5

// ---------------- scratch (device globals; no allocation allowed) -------------
__device__ float d_g_src[NR*EE];
__device__ float d_h2[NN*2*EE];        // [N, 512] = [g2 | h_src]
__device__ float d_gram[NN*1024];
__device__ float d_t1[NN*512];
__device__ float d_qb[NN*EE];
__device__ float d_kb[NN*EE];
__device__ float d_vb[NN*EE];
__device__ float d_vgb[NR*EE];
__device__ float d_outv[NN*EE];
__device__ float d_outg[NR*EE];
__device__ float d_hnew[NN*EE];
__device__ float d_gnew[NR*EE];
// fp16-packed attention operands
__device__ uint32_t d_kh[NN*128];      // K hi, half2 words: [node][128]
__device__ uint32_t d_kl[NN*128];      // K lo
__device__ __half  d_vt[HH*128*NN];    // combined V transposed: [h][c=128][node]

// ---------------- helpers ------------------------------------------------------
__device__ __forceinline__ uint32_t packh2(__half a, __half b) {
    __half2 t = __halves2half2(a, b);
    return *reinterpret_cast<uint32_t*>(&t);
}
__device__ __forceinline__ uint32_t cvth(float a, float b) {
    __half2 t = __floats2half2_rn(a, b);
    return *reinterpret_cast<uint32_t*>(&t);
}
__device__ __forceinline__ void cvthl(float a, float b, uint32_t& hi, uint32_t& lo) {
    __half ha = __float2half_rn(a), hb = __float2half_rn(b);
    __half la = __float2half_rn(a - __half2float(ha));
    __half lb = __float2half_rn(b - __half2float(hb));
    hi = packh2(ha, hb);
    lo = packh2(la, lb);
}

__device__ __forceinline__ void mma_f16(float c[4],
    uint32_t a0, uint32_t a1, uint32_t a2, uint32_t a3,
    uint32_t b0, uint32_t b1)
{
    asm volatile(
        "mma.sync.aligned.m16n8k16.row.col.f32.f16.f16.f32 "
        "{%0,%1,%2,%3}, {%4,%5,%6,%7}, {%8,%9}, {%0,%1,%2,%3};\n"
        : "+f"(c[0]), "+f"(c[1]), "+f"(c[2]), "+f"(c[3])
        : "r"(a0), "r"(a1), "r"(a2), "r"(a3), "r"(b0), "r"(b1));
}

__device__ __forceinline__ void ldsm4(uint32_t& r0, uint32_t& r1,
                                      uint32_t& r2, uint32_t& r3, const void* p)
{
    uint32_t addr = (uint32_t)__cvta_generic_to_shared(p);
    asm volatile("ldmatrix.sync.aligned.m8n8.x4.shared.b16 {%0,%1,%2,%3}, [%4];"
                 : "=r"(r0), "=r"(r1), "=r"(r2), "=r"(r3) : "r"(addr));
}

// ---------------- g_src = (equ @ W_equ) * 16 ----------------------------------
__global__ void gsrc_kernel(const float* __restrict__ equ,
                            const float* __restrict__ W_equ)
{
    __shared__ float es[MM];
    int r = blockIdx.x;
    int e = threadIdx.x;
    if (e < MM) es[e] = equ[r*MM + e];
    __syncthreads();
    float acc = 0.f;
#pragma unroll
    for (int m = 0; m < MM; m++) acc += es[m] * W_equ[m*EE + e];
    d_g_src[r*EE + e] = acc * SQRT_E;
}

// ---------------- h_src = h*16  (into h2[:,256:512]) --------------------------
__global__ void hsrc_kernel(const float* __restrict__ h)
{
    int i = blockIdx.x, e = threadIdx.x;
    d_h2[i*512 + 256 + e] = h[i*EE + e] * SQRT_E;
}

// ---------------- g2p + Gram ---------------------------------------------------
__global__ void gram_kernel(const float* __restrict__ W_gproj)
{
    __shared__ float gs[NV][EE];
    __shared__ float g2p[NV][32];
    int node = blockIdx.x;
    int t = threadIdx.x;
#pragma unroll
    for (int i = 0; i < NV; i++) gs[i][t] = d_g_src[(node*NV + i)*EE + t];
    __syncthreads();
    if (t < 96) {
        int i = t >> 5, a = t & 31;
        float acc = 0.f;
#pragma unroll 4
        for (int k2 = 0; k2 < EE; k2++) acc += gs[i][k2] * W_gproj[k2*32 + a];
        g2p[i][a] = acc;
    }
    __syncthreads();
#pragma unroll
    for (int o = t; o < 1024; o += 256) {
        int a = o >> 5, b = o & 31;
        float acc = g2p[0][a]*g2p[0][b] + g2p[1][a]*g2p[1][b] + g2p[2][a]*g2p[2][b];
        d_gram[node*1024 + o] = acc;
    }
}

// ---------------- fp16 tensor-core GEMM: 128x64 tile, warp 32x32 ---------------
// C[row*ldc+col] = post( alpha*(A@B + bias) + resid[row*ldr+col] )
// A row-major [M,K], B row-major [K,Nn]. K-chunk 32, m16n8k16.
template<bool RELU, bool BIAS, bool RES, bool X2>
__global__ __launch_bounds__(256, 2)
void gemm16(const float* __restrict__ A, const float* __restrict__ B,
            const float* __restrict__ bias, const float* __restrict__ resid,
            float* __restrict__ C, int K, int Nn,
            int ldr, int ldc, float alpha)
{
    __shared__ uint32_t Ahi[128][20];  // [m][k half2]
    __shared__ uint32_t Alo[128][20];
    __shared__ uint32_t Bhi[64][20];   // TRANSPOSED: [n][k half2]
    __shared__ uint32_t Blo[64][20];

    int tid = threadIdx.x, lane = tid & 31, w = tid >> 5;
    int m0 = blockIdx.y * 128, n0 = blockIdx.x * 64;
    int rw = (w >> 1) * 32;    // warp row base (0,32,64,96)
    int cw = (w & 1) * 32;     // warp col base (0,32)
    int g  = lane >> 3;

    int afr = tid >> 1;          // A fill: row 0..127
    int afq = tid & 1;           // A fill: k-half (16 floats)
    int bfn = tid & 63;          // B fill: col n 0..63
    int bfk = tid >> 6;          // B fill: k-group (8 floats)

    float acc[2][4][4] = {};
    float4 pa[4];
    float pb[8];

    // prologue prefetch (k0 = 0)
    {
        const float4* ap = (const float4*)&A[(m0 + afr)*K + afq*16];
        pa[0] = ap[0]; pa[1] = ap[1]; pa[2] = ap[2]; pa[3] = ap[3];
#pragma unroll
        for (int i = 0; i < 8; i++) pb[i] = B[(bfk*8 + i)*Nn + n0 + bfn];
    }

    for (int k0 = 0; k0 < K; k0 += 32) {
        __syncthreads();
        // store prefetched A (fp32 -> fp16 hi[/lo])
#pragma unroll
        for (int t = 0; t < 4; t++) {
            if (X2) {
                uint32_t h0,l0,h1,l1;
                cvthl(pa[t].x, pa[t].y, h0, l0);
                cvthl(pa[t].z, pa[t].w, h1, l1);
                *(uint2*)&Ahi[afr][afq*8 + t*2] = make_uint2(h0, h1);
                *(uint2*)&Alo[afr][afq*8 + t*2] = make_uint2(l0, l1);
            } else {
                *(uint2*)&Ahi[afr][afq*8 + t*2] =
                    make_uint2(cvth(pa[t].x, pa[t].y), cvth(pa[t].z, pa[t].w));
            }
        }
        // store prefetched B
        if (X2) {
            uint32_t h0,l0,h1,l1;
            cvthl(pb[0], pb[1], h0, l0); cvthl(pb[2], pb[3], h1, l1);
            *(uint2*)&Bhi[bfn][bfk*4]   = make_uint2(h0,h1);
            *(uint2*)&Blo[bfn][bfk*4]   = make_uint2(l0,l1);
            cvthl(pb[4], pb[5], h0, l0); cvthl(pb[6], pb[7], h1, l1);
            *(uint2*)&Bhi[bfn][bfk*4+2] = make_uint2(h0,h1);
            *(uint2*)&Blo[bfn][bfk*4+2] = make_uint2(l0,l1);
        } else {
            *(uint2*)&Bhi[bfn][bfk*4]   = make_uint2(cvth(pb[0],pb[1]), cvth(pb[2],pb[3]));
            *(uint2*)&Bhi[bfn][bfk*4+2] = make_uint2(cvth(pb[4],pb[5]), cvth(pb[6],pb[7]));
        }
        __syncthreads();
        // prefetch next chunk during compute
        if (k0 + 32 < K) {
            const float4* ap = (const float4*)&A[(m0 + afr)*K + k0 + 32 + afq*16];
            pa[0] = ap[0]; pa[1] = ap[1]; pa[2] = ap[2]; pa[3] = ap[3];
#pragma unroll
            for (int i = 0; i < 8; i++) pb[i] = B[(k0 + 32 + bfk*8 + i)*Nn + n0 + bfn];
        }
#pragma unroll
        for (int kk = 0; kk < 2; kk++) {
            int arow = rw + (g&1)*8 + (lane&7);
            int acol = kk*8 + (g>>1)*4;
            uint32_t ah[2][4], al[2][4];
            ldsm4(ah[0][0],ah[0][1],ah[0][2],ah[0][3], &Ahi[arow][acol]);
            ldsm4(ah[1][0],ah[1][1],ah[1][2],ah[1][3], &Ahi[arow+16][acol]);
            if (X2) {
                ldsm4(al[0][0],al[0][1],al[0][2],al[0][3], &Alo[arow][acol]);
                ldsm4(al[1][0],al[1][1],al[1][2],al[1][3], &Alo[arow+16][acol]);
            }
            uint32_t bh[8], bl[8];
#pragma unroll
            for (int jj = 0; jj < 2; jj++) {
                int brow = cw + jj*16 + (g>>1)*8 + (lane&7);
                int bcol = kk*8 + (g&1)*4;
                ldsm4(bh[jj*4+0],bh[jj*4+1],bh[jj*4+2],bh[jj*4+3], &Bhi[brow][bcol]);
                if (X2)
                    ldsm4(bl[jj*4+0],bl[jj*4+1],bl[jj*4+2],bl[jj*4+3], &Blo[brow][bcol]);
            }
#pragma unroll
            for (int t = 0; t < 2; t++) {
#pragma unroll
                for (int j = 0; j < 4; j++) {
                    uint32_t b0 = bh[(j>>1)*4 + (j&1)*2], b1 = bh[(j>>1)*4 + (j&1)*2 + 1];
                    mma_f16(acc[t][j], ah[t][0],ah[t][1],ah[t][2],ah[t][3], b0, b1);
                    if (X2) {
                        uint32_t c0 = bl[(j>>1)*4 + (j&1)*2], c1 = bl[(j>>1)*4 + (j&1)*2 + 1];
                        mma_f16(acc[t][j], al[t][0],al[t][1],al[t][2],al[t][3], b0, b1);
                        mma_f16(acc[t][j], ah[t][0],ah[t][1],ah[t][2],ah[t][3], c0, c1);
                    }
                }
            }
        }
    }

    // epilogue
#pragma unroll
    for (int t = 0; t < 2; t++) {
        int r0 = m0 + rw + t*16 + (lane >> 2);
#pragma unroll
        for (int j = 0; j < 4; j++) {
            int col = n0 + cw + j*8 + 2*(lane & 3);
            float b0 = 0.f, b1 = 0.f;
            if (BIAS) { b0 = bias[col]; b1 = bias[col+1]; }
#pragma unroll
            for (int h2r = 0; h2r < 2; h2r++) {
                int row = r0 + h2r*8;
                float v0 = acc[t][j][2*h2r+0];
                float v1 = acc[t][j][2*h2r+1];
                if (BIAS) { v0 += b0; v1 += b1; }
                v0 *= alpha; v1 *= alpha;
                if (RES) {
                    v0 += resid[row*ldr + col];
                    v1 += resid[row*ldr + col + 1];
                }
                if (RELU) { v0 = fmaxf(v0, 0.f); v1 = fmaxf(v1, 0.f); }
                *(float2*)&C[row*ldc + col] = make_float2(v0, v1);
            }
        }
    }
}

// ---------------- pack kernels -------------------------------------------------
__global__ void pack_k_kernel()
{
    int idx = blockIdx.x * 256 + threadIdx.x;     // over NN*128
    float a = d_kb[idx*2], b = d_kb[idx*2+1];
    cvthl(a, b, d_kh[idx], d_kl[idx]);
}

// combined V transposed: d_vt[h][c][node], c: 0..31 = v head-dim, 32..127 = vg
__global__ void pack_v_kernel()
{
    int idx = blockIdx.x * 256 + threadIdx.x;     // over HH*128*NN
    int node = idx & (NN-1);
    int hc = idx >> 12;
    int h = hc >> 7, c = hc & 127;
    float s;
    if (c < 32) s = d_vb[node*EE + h*DD + c];
    else {
        int iv = (c - 32) >> 5, dc = (c - 32) & 31;
        s = d_vgb[(node*NV + iv)*EE + h*DD + dc];
    }
    d_vt[idx] = __float2half_rn(s);
}

// ---------------- register-resident fp16 flash attention -----------------------
// 4 warps / CTA, TQ=64: each warp owns 16 query rows x full 64-wide S in regs.
#define ATQ 64
#define ATK 64
#define AT2_SMEM_BYTES ((64*20*2 + 128*36)*4)

__global__ __launch_bounds__(128, 3)
void attn_reg_kernel(const float* __restrict__ q)
{
    extern __shared__ char smc[];
    uint32_t* KH = (uint32_t*)smc;                // [64][20] half2
    uint32_t* KL = KH + 64*20;
    uint32_t* VT = KL + 64*20;                    // [128][36] half2 (n-major, k contig)

    int tid  = threadIdx.x;
    int lane = tid & 31;
    int w    = tid >> 5;         // 0..3
    int g    = lane >> 3;
    int hh   = blockIdx.y;
    int hoff = hh * DD;
    int qbase = blockIdx.x * ATQ;
    int wbase = w * 16;          // warp's 16 query rows

    // ---- preload Q fragments fp16 hi/lo (2 k16 chunks) ----
    uint32_t qh[2][4], ql[2][4];
    {
        int gr0 = qbase + wbase + (lane >> 2);
#pragma unroll
        for (int kk = 0; kk < 2; kk++) {
            int c0 = hoff + kk*16 + 2*(lane & 3);
            float2 x0 = *(const float2*)&q[gr0*EE + c0];
            float2 x1 = *(const float2*)&q[(gr0+8)*EE + c0];
            float2 x2 = *(const float2*)&q[gr0*EE + c0 + 8];
            float2 x3 = *(const float2*)&q[(gr0+8)*EE + c0 + 8];
            cvthl(x0.x, x0.y, qh[kk][0], ql[kk][0]);
            cvthl(x1.x, x1.y, qh[kk][1], ql[kk][1]);
            cvthl(x2.x, x2.y, qh[kk][2], ql[kk][2]);
            cvthl(x3.x, x3.y, qh[kk][3], ql[kk][3]);
        }
    }

    float rmax0 = -1e30f, rmax1 = -1e30f;
    float rsum0 = 0.f, rsum1 = 0.f;
    float acc[16][4] = {};       // 16 n8-frags covering 128 out cols

    for (int kb = 0; kb < NN; kb += ATK) {
        __syncthreads();
        // ---- fill K tile from packed global (hi/lo), 128 threads ----
#pragma unroll
        for (int l = 0; l < 4; l++) {
            int idx = tid + l*128;
            int row = idx >> 3, cp = (idx & 7) * 2;
            int gg = (kb + row)*128 + hh*16 + cp;
            *(uint2*)&KH[row*20 + cp] = *(const uint2*)&d_kh[gg];
            *(uint2*)&KL[row*20 + cp] = *(const uint2*)&d_kl[gg];
        }
        // ---- fill combined V tile (transposed, contiguous in k) ----
#pragma unroll
        for (int l = 0; l < 8; l++) {
            int idx = tid + l*128;
            int row = idx >> 3;          // 0..127 (out col)
            int c16 = idx & 7;           // 8-half chunk
            uint4 vv = *(const uint4*)&d_vt[(hh*128 + row)*NN + kb + c16*8];
            *(uint4*)&VT[row*36 + c16*4] = vv;
        }
        __syncthreads();

        // ---- S = Q K^T (fp16 hi/lo): warp computes 16 rows x 64 cols ----
        float sc[8][4];
#pragma unroll
        for (int j = 0; j < 8; j++)
#pragma unroll
            for (int i = 0; i < 4; i++) sc[j][i] = 0.f;
#pragma unroll
        for (int kk = 0; kk < 2; kk++) {
#pragma unroll
            for (int jj = 0; jj < 4; jj++) {
                int nrow = jj*16 + (g>>1)*8 + (lane&7);
                int kc   = kk*8 + (g&1)*4;
                uint32_t bh[4], bl[4];
                ldsm4(bh[0],bh[1],bh[2],bh[3], &KH[nrow*20 + kc]);
                ldsm4(bl[0],bl[1],bl[2],bl[3], &KL[nrow*20 + kc]);
#pragma unroll
                for (int jw = 0; jw < 2; jw++) {
                    int j = 2*jj + jw;
                    uint32_t b0 = bh[jw*2], b1 = bh[jw*2+1];
                    uint32_t c0 = bl[jw*2], c1 = bl[jw*2+1];
                    mma_f16(sc[j], qh[kk][0], qh[kk][1], qh[kk][2], qh[kk][3], b0, b1);
                    mma_f16(sc[j], ql[kk][0], ql[kk][1], ql[kk][2], ql[kk][3], b0, b1);
                    mma_f16(sc[j], qh[kk][0], qh[kk][1], qh[kk][2], qh[kk][3], c0, c1);
                }
            }
        }

        // ---- online softmax in registers; skip rescale if no new max ----
        float m0 = rmax0, m1 = rmax1;
#pragma unroll
        for (int j = 0; j < 8; j++) {
            m0 = fmaxf(m0, fmaxf(sc[j][0], sc[j][1]));
            m1 = fmaxf(m1, fmaxf(sc[j][2], sc[j][3]));
        }
        m0 = fmaxf(m0, __shfl_xor_sync(0xffffffffu, m0, 1));
        m0 = fmaxf(m0, __shfl_xor_sync(0xffffffffu, m0, 2));
        m1 = fmaxf(m1, __shfl_xor_sync(0xffffffffu, m1, 1));
        m1 = fmaxf(m1, __shfl_xor_sync(0xffffffffu, m1, 2));

        bool nm = __any_sync(0xffffffffu, (m0 > rmax0) || (m1 > rmax1));
        if (nm) {
            float alf0 = __expf(rmax0 - m0);
            float alf1 = __expf(rmax1 - m1);
            rsum0 *= alf0; rsum1 *= alf1;
#pragma unroll
            for (int j = 0; j < 16; j++) {
                acc[j][0] *= alf0; acc[j][1] *= alf0;
                acc[j][2] *= alf1; acc[j][3] *= alf1;
            }
            rmax0 = m0; rmax1 = m1;
        }

        uint32_t pp0[8], pp1[8];
        float ps0 = 0.f, ps1 = 0.f;
#pragma unroll
        for (int j = 0; j < 8; j++) {
            float pa = __expf(sc[j][0] - rmax0);
            float pb = __expf(sc[j][1] - rmax0);
            float pc = __expf(sc[j][2] - rmax1);
            float pd = __expf(sc[j][3] - rmax1);
            pp0[j] = cvth(pa, pb);
            pp1[j] = cvth(pc, pd);
            ps0 += pa + pb;
            ps1 += pc + pd;
        }
        ps0 += __shfl_xor_sync(0xffffffffu, ps0, 1);
        ps0 += __shfl_xor_sync(0xffffffffu, ps0, 2);
        ps1 += __shfl_xor_sync(0xffffffffu, ps1, 1);
        ps1 += __shfl_xor_sync(0xffffffffu, ps1, 2);
        rsum0 += ps0;
        rsum1 += ps1;

        // ---- P@V (single fp16), P register-resident as A-frags ----
#pragma unroll
        for (int kk = 0; kk < 4; kk++) {
            uint32_t a0 = pp0[2*kk],   a1 = pp1[2*kk];
            uint32_t a2 = pp0[2*kk+1], a3 = pp1[2*kk+1];
#pragma unroll
            for (int jj = 0; jj < 8; jj++) {
                int nrow = jj*16 + (g>>1)*8 + (lane&7);
                int kc   = kk*8 + (g&1)*4;
                uint32_t b[4];
                ldsm4(b[0], b[1], b[2], b[3], &VT[nrow*36 + kc]);
                mma_f16(acc[2*jj],   a0, a1, a2, a3, b[0], b[1]);
                mma_f16(acc[2*jj+1], a0, a1, a2, a3, b[2], b[3]);
            }
        }
    }

    // ---- epilogue: normalize and scatter ----
    {
        float inv0 = 1.0f / rsum0;
        float inv1 = 1.0f / rsum1;
        int gr0 = qbase + wbase + (lane >> 2);
        int gr1 = gr0 + 8;
#pragma unroll
        for (int j = 0; j < 16; j++) {
            int col = j*8 + 2*(lane & 3);
            float2 v0 = make_float2(acc[j][0]*inv0, acc[j][1]*inv0);
            float2 v1 = make_float2(acc[j][2]*inv1, acc[j][3]*inv1);
            if (col < 32) {
                *(float2*)&d_outv[gr0*EE + hoff + col] = v0;
                *(float2*)&d_outv[gr1*EE + hoff + col] = v1;
            } else {
                int iv = (col - 32) >> 5, dc = (col - 32) & 31;
                *(float2*)&d_outg[(gr0*NV + iv)*EE + hoff + dc] = v0;
                *(float2*)&d_outg[(gr1*NV + iv)*EE + hoff + dc] = v1;
            }
        }
    }
}

// ---------------- equ_out = gnew @ W_gdec  ([*,256]@[256,16]) ------------------
__global__ void gdec_kernel(const float* __restrict__ W_gdec, float* __restrict__ out)
{
    __shared__ float gs[16][EE];
    int rbase = blockIdx.x * 16;
    int t = threadIdx.x;
    for (int idx = t; idx < 16*EE; idx += 256)
        gs[idx >> 8][idx & 255] = d_gnew[(rbase + (idx >> 8))*EE + (idx & 255)];
    __syncthreads();
    int lr = t >> 4, c = t & 15;
    float acc = 0.f;
#pragma unroll 4
    for (int k2 = 0; k2 < EE; k2++) acc += gs[lr][k2] * W_gdec[k2*MM + c];
    out[(rbase + lr)*MM + c] = acc;
}

// ------------------------------------------------------------------------------
extern "C" void kernel_launch(void* const* d_in, const int* in_sizes, int n_in,
                              void* d_out, int out_size)
{
    const float* equ    = (const float*)d_in[0];
    const float* h      = (const float*)d_in[1];
    const float* W_equ  = (const float*)d_in[4];
    const float* W_gproj= (const float*)d_in[5];
    const float* W_vg   = (const float*)d_in[6];
    const float* W_g1   = (const float*)d_in[7];
    const float* b_g1   = (const float*)d_in[8];
    const float* W_g2   = (const float*)d_in[9];
    const float* b_g2   = (const float*)d_in[10];
    const float* W_q    = (const float*)d_in[11];
    const float* b_q    = (const float*)d_in[12];
    const float* W_k    = (const float*)d_in[13];
    const float* b_k    = (const float*)d_in[14];
    const float* W_v    = (const float*)d_in[15];
    const float* b_v    = (const float*)d_in[16];
    const float* W_ng   = (const float*)d_in[17];
    const float* b_ng   = (const float*)d_in[18];
    const float* W_gout = (const float*)d_in[19];
    const float* W_gdec = (const float*)d_in[20];
    const float* W_hdec = (const float*)d_in[21];
    const float* b_hdec = (const float*)d_in[22];
    float* out = (float*)d_out;

    float *g_src, *h2, *gram, *t1, *qb, *kb, *vb, *vgb, *outv, *outg, *hnew, *gnew;
    cudaGetSymbolAddress((void**)&g_src, d_g_src);
    cudaGetSymbolAddress((void**)&h2,    d_h2);
    cudaGetSymbolAddress((void**)&gram,  d_gram);
    cudaGetSymbolAddress((void**)&t1,    d_t1);
    cudaGetSymbolAddress((void**)&qb,    d_qb);
    cudaGetSymbolAddress((void**)&kb,    d_kb);
    cudaGetSymbolAddress((void**)&vb,    d_vb);
    cudaGetSymbolAddress((void**)&vgb,   d_vgb);
    cudaGetSymbolAddress((void**)&outv,  d_outv);
    cudaGetSymbolAddress((void**)&outg,  d_outg);
    cudaGetSymbolAddress((void**)&hnew,  d_hnew);
    cudaGetSymbolAddress((void**)&gnew,  d_gnew);

    // 1) prep
    gsrc_kernel<<<NR, 256>>>(equ, W_equ);
    hsrc_kernel<<<NN, 256>>>(h);
    gram_kernel<<<NN, 256>>>(W_gproj);

    // 2) MLP on gram (logit-critical -> X2)
    gemm16<true, true, false, true><<<dim3(512/64, NN/128), 256>>>(
        gram, W_g1, b_g1, nullptr, t1, 1024, 512, 0, 512, 1.f);
    gemm16<false, true, false, true><<<dim3(256/64, NN/128), 256>>>(
        t1, W_g2, b_g2, nullptr, h2, 512, 256, 0, 512, 1.f);

    // 3) q,k (X2), v,vg (single)
    gemm16<false, true, false, true><<<dim3(256/64, NN/128), 256>>>(
        h2, W_q, b_q, nullptr, qb, 512, 256, 0, 256, SCALING);
    gemm16<false, true, false, true><<<dim3(256/64, NN/128), 256>>>(
        h2, W_k, b_k, nullptr, kb, 512, 256, 0, 256, 1.f);
    gemm16<false, true, false, false><<<dim3(256/64, NN/128), 256>>>(
        h2, W_v, b_v, nullptr, vb, 512, 256, 0, 256, 1.f);
    gemm16<false, false, false, false><<<dim3(256/64, NR/128), 256>>>(
        g_src, W_vg, nullptr, nullptr, vgb, 256, 256, 0, 256, 1.f);

    // 3b) pack K (hi/lo fp16) and combined V (fp16, transposed)
    pack_k_kernel<<<NN*128/256, 256>>>();
    pack_v_kernel<<<HH*128*NN/256, 256>>>();

    // 4) register-resident fp16 flash attention
    cudaFuncSetAttribute(attn_reg_kernel, cudaFuncAttributeMaxDynamicSharedMemorySize,
                         AT2_SMEM_BYTES);
    attn_reg_kernel<<<dim3(NN/ATQ, HH), 128, AT2_SMEM_BYTES>>>(qb);

    // 5) h path (single)
    gemm16<false, true, true, false><<<dim3(256/64, NN/128), 256>>>(
        outv, W_ng, b_ng, h2 + 256, hnew, 256, 256, 512, 256, 1.f);
    gemm16<false, true, false, false><<<dim3(256/64, NN/128), 256>>>(
        hnew, W_hdec, b_hdec, nullptr, out + NR*MM, 256, 256, 0, 256, 1.f);

    // 6) g path (single)
    gemm16<false, false, true, false><<<dim3(256/64, NR/128), 256>>>(
        outg, W_gout, nullptr, g_src, gnew, 256, 256, 256, 256, 1.f);
    gdec_kernel<<<NR/16, 256>>>(W_gdec, out);
}